// round 5
// baseline (speedup 1.0000x reference)
#include <cuda_runtime.h>
#include <cstddef>
#include <cstdint>

#define N_LANE  20000
#define P_LANE  20
#define N_AGENT 4000
#define T_AGENT 20
#define F_DIM   8
#define H_DIM   128
#define E_LL    640000
#define E_AA    128000
#define E_LA    200000

// ---------------- scratch (device globals; no allocation allowed) -----------
__device__ float g_lane_enc [N_LANE  * H_DIM];
__device__ float g_agent_enc[N_AGENT * H_DIM];
__device__ float g_lane_agg [N_LANE  * H_DIM];
__device__ float g_agent_agg[N_AGENT * H_DIM];
__device__ float g_ms      [N_LANE  * H_DIM];
__device__ float g_deg_l[N_LANE];
__device__ float g_deg_a[N_AGENT];

// ---------------- tf32 mma.sync helpers --------------------------------------
__device__ __forceinline__ uint32_t f2tf32(float f) {
    uint32_t u;
    asm("cvt.rna.tf32.f32 %0, %1;" : "=r"(u) : "f"(f));
    return u;
}
__device__ __forceinline__ void mma_tf32(float c[4], const uint32_t a[4],
                                         uint32_t b0, uint32_t b1) {
    asm("mma.sync.aligned.m16n8k8.row.col.f32.tf32.tf32.f32 "
        "{%0,%1,%2,%3}, {%4,%5,%6,%7}, {%8,%9}, {%0,%1,%2,%3};"
        : "+f"(c[0]), "+f"(c[1]), "+f"(c[2]), "+f"(c[3])
        : "r"(a[0]), "r"(a[1]), "r"(a[2]), "r"(a[3]), "r"(b0), "r"(b1));
}

// ---------------- packed f32x2 helpers (GNN path) ----------------------------
__device__ __forceinline__ void ffma2(unsigned long long& d,
                                      unsigned long long a,
                                      unsigned long long b) {
    asm("fma.rn.f32x2 %0, %1, %2, %0;" : "+l"(d) : "l"(a), "l"(b));
}
__device__ __forceinline__ unsigned long long pack_dup(float x) {
    unsigned long long r;
    unsigned u = __float_as_uint(x);
    asm("mov.b64 %0, {%1, %2};" : "=l"(r) : "r"(u), "r"(u));
    return r;
}
__device__ __forceinline__ float2 unpack2(unsigned long long v) {
    unsigned lo, hi;
    asm("mov.b64 {%0, %1}, %2;" : "=r"(lo), "=r"(hi) : "l"(v));
    return make_float2(__uint_as_float(lo), __uint_as_float(hi));
}

// ---------------- zero kernels ----------------------------------------------
__global__ void zero_all_kernel() {
    int i = blockIdx.x * blockDim.x + threadIdx.x;
    int stride = gridDim.x * blockDim.x;
    for (int k = i; k < N_LANE * H_DIM; k += stride) g_lane_agg[k] = 0.f;
    for (int k = i; k < N_AGENT * H_DIM; k += stride) g_agent_agg[k] = 0.f;
    for (int k = i; k < N_LANE; k += stride) g_deg_l[k] = 0.f;
    for (int k = i; k < N_AGENT; k += stride) g_deg_a[k] = 0.f;
}
__global__ void zero_agent_kernel() {
    int i = blockIdx.x * blockDim.x + threadIdx.x;
    int stride = gridDim.x * blockDim.x;
    for (int k = i; k < N_AGENT * H_DIM; k += stride) g_agent_agg[k] = 0.f;
    for (int k = i; k < N_AGENT; k += stride) g_deg_a[k] = 0.f;
}

// ---------------- shared Bperm init ------------------------------------------
// Fragment-permuted B: chunk (wn*16+kc) holds 64 cols x 8 k as 32 lanes x 16
// contiguous regs: reg = nt*2+p -> element (k = kc*8 + tq + 4p, n = wn*64 + nt*8 + tg)
__device__ __forceinline__ void load_Bperm(uint32_t* Bpu, const float* __restrict__ w,
                                           int tid, int nthreads) {
    for (int idx = tid; idx < 16384; idx += nthreads) {
        const int kcn  = idx >> 9;
        const int lane = (idx >> 4) & 31;
        const int reg  = idx & 15;
        const int kc = kcn & 15, wn = kcn >> 4;
        const int tg = lane >> 2, tq = lane & 3;
        const int nt = reg >> 1, p = reg & 1;
        const int k = kc * 8 + tq + 4 * p;
        const int n = wn * 64 + nt * 8 + tg;
        Bpu[idx] = f2tf32(w[k * H_DIM + n]);
    }
}

// ---------------- tensor encoder (stages 1+2+max), 512 threads ---------------
#define ENC_TILE_NODES 6
#define SA 132
#define ENC3_SMEM_FLOATS (16896 + 16384 + 960 + 1024 + 128 + 128 + 16)
#define ENC3_SMEM_BYTES  (ENC3_SMEM_FLOATS * 4)

__global__ void __launch_bounds__(512, 1)
enc_mma_kernel(const float* __restrict__ x_in,
               const float* __restrict__ w1, const float* __restrict__ b1,
               const float* __restrict__ w2, const float* __restrict__ b2,
               float* __restrict__ ms_out, int n_nodes, int n_tiles)
{
    extern __shared__ float smem[];
    float* A     = smem;               // tf32 bits during mma; f32 Dbuf after
    float* Bperm = A + 16896;          // 16384
    float* xs    = Bperm + 16384;
    float* w1s   = xs + 960;
    float* b1s   = w1s + 1024;
    float* b2s   = b1s + 128;
    float* refv  = b2s + 128;

    uint32_t* Au  = (uint32_t*)A;
    uint32_t* Bpu = (uint32_t*)Bperm;

    const int tid  = threadIdx.x;      // 0..511
    const int wid  = tid >> 5;         // 0..15
    const int lane = tid & 31;
    const int tg = lane >> 2;
    const int tq = lane & 3;
    const int warp_m = wid & 7;        // 8 x 16-row tiles
    const int warp_n = wid >> 3;       // 2 x 64-col tiles

    load_Bperm(Bpu, w2, tid, 512);
    for (int i = tid; i < F_DIM * H_DIM; i += 512) w1s[i] = w1[i];
    if (tid < H_DIM) { b1s[tid] = b1[tid]; b2s[tid] = b2[tid]; }
    __syncthreads();

    const int c    = tid & 127;
    const int rgrp = tid >> 7;         // 0..3, 30 rows each
    float wa[F_DIM];
#pragma unroll
    for (int f = 0; f < F_DIM; f++) wa[f] = w1s[f * H_DIM + c];
    const float b1v = b1s[c];

    for (int tile = blockIdx.x; tile < n_tiles; tile += gridDim.x) {
        const int node0 = tile * ENC_TILE_NODES;

        // ---- load x (6 nodes x 160), clamped ----
        for (int i = tid; i < ENC_TILE_NODES * P_LANE * F_DIM; i += 512) {
            int j = i / (P_LANE * F_DIM);
            int nd = node0 + j; if (nd >= n_nodes) nd = n_nodes - 1;
            xs[i] = x_in[(size_t)nd * (P_LANE * F_DIM) + (i - j * (P_LANE * F_DIM))];
        }
        __syncthreads();
        if (tid < 2 * ENC_TILE_NODES)
            refv[tid] = xs[(tid >> 1) * 160 + 19 * 8 + (tid & 1)];
        __syncthreads();
        if (tid < 240) {
            int j = tid / 40, rem = tid % 40, t = rem >> 1, f = rem & 1;
            xs[j * 160 + t * 8 + f] -= refv[j * 2 + f];
        }
        __syncthreads();

        // ---- stage 1: A(r,c) = tf32(relu(b1 + x'[r].w1[:,c])), rows 0..119 ----
#pragma unroll 3
        for (int i = 0; i < 30; i++) {
            const int r = rgrp * 30 + i;
            const float4* xp = (const float4*)(xs + r * 8);
            const float4 x0 = xp[0], x1 = xp[1];
            float s = b1v;
            s = fmaf(x0.x, wa[0], s); s = fmaf(x0.y, wa[1], s);
            s = fmaf(x0.z, wa[2], s); s = fmaf(x0.w, wa[3], s);
            s = fmaf(x1.x, wa[4], s); s = fmaf(x1.y, wa[5], s);
            s = fmaf(x1.z, wa[6], s); s = fmaf(x1.w, wa[7], s);
            Au[r * SA + c] = f2tf32(fmaxf(s, 0.f));
        }
        // zero pad rows 120..127
        for (int i = tid; i < 8 * 128; i += 512)
            Au[(120 + (i >> 7)) * SA + (i & 127)] = 0;
        __syncthreads();

        // ---- mma: D[128x128] = A @ B, warp tile 16x64 ----
        float cfr[8][4];
#pragma unroll
        for (int nt = 0; nt < 8; nt++)
#pragma unroll
            for (int q = 0; q < 4; q++) cfr[nt][q] = 0.f;

        const int rm = warp_m * 16;
#pragma unroll 4
        for (int kc = 0; kc < 16; kc++) {
            const int k0 = kc * 8;
            uint32_t afr[4];
            afr[0] = Au[(rm + tg) * SA + k0 + tq];
            afr[1] = Au[(rm + tg + 8) * SA + k0 + tq];
            afr[2] = Au[(rm + tg) * SA + k0 + tq + 4];
            afr[3] = Au[(rm + tg + 8) * SA + k0 + tq + 4];
            const uint4* bp = (const uint4*)(Bpu + (((warp_n << 4) + kc) << 9) + (lane << 4));
            const uint4 q0 = bp[0], q1 = bp[1], q2 = bp[2], q3 = bp[3];
            mma_tf32(cfr[0], afr, q0.x, q0.y);
            mma_tf32(cfr[1], afr, q0.z, q0.w);
            mma_tf32(cfr[2], afr, q1.x, q1.y);
            mma_tf32(cfr[3], afr, q1.z, q1.w);
            mma_tf32(cfr[4], afr, q2.x, q2.y);
            mma_tf32(cfr[5], afr, q2.z, q2.w);
            mma_tf32(cfr[6], afr, q3.x, q3.y);
            mma_tf32(cfr[7], afr, q3.z, q3.w);
        }
        __syncthreads();   // all A reads done; A memory becomes Dbuf

        // ---- store C frags to Dbuf ----
        {
            const int rr = rm + tg;
#pragma unroll
            for (int nt = 0; nt < 8; nt++) {
                const int cc = warp_n * 64 + nt * 8 + 2 * tq;
                *(float2*)(A + rr * SA + cc)       = make_float2(cfr[nt][0], cfr[nt][1]);
                *(float2*)(A + (rr + 8) * SA + cc) = make_float2(cfr[nt][2], cfr[nt][3]);
            }
        }
        __syncthreads();

        // ---- per-node max over 20 rows + bias + relu -> g_ms ----
        for (int task = tid; task < ENC_TILE_NODES * H_DIM; task += 512) {
            const int j = task >> 7, cc = task & 127;
            const int nd = node0 + j;
            if (nd < n_nodes) {
                float m = -3.4e38f;
                const float* dp = A + (j * 20) * SA + cc;
#pragma unroll
                for (int r = 0; r < 20; r++) m = fmaxf(m, dp[r * SA]);
                ms_out[(size_t)nd * H_DIM + cc] = fmaxf(m + b2s[cc], 0.f);
            }
        }
        __syncthreads();
    }
}

// ---------------- tensor MLP: out = relu(in @ w + b), 128-row tiles ----------
#define MLP2_SMEM_FLOATS (16896 + 16384 + 128)
#define MLP2_SMEM_BYTES  (MLP2_SMEM_FLOATS * 4)

__global__ void __launch_bounds__(512, 1)
mlp_mma_kernel(const float* __restrict__ in_feat,
               const float* __restrict__ w, const float* __restrict__ b,
               float* __restrict__ out, int n_nodes)
{
    extern __shared__ float smem[];
    float* A     = smem;
    float* Bperm = A + 16896;
    float* bs    = Bperm + 16384;
    uint32_t* Au  = (uint32_t*)A;
    uint32_t* Bpu = (uint32_t*)Bperm;

    const int tid  = threadIdx.x;
    const int wid  = tid >> 5;
    const int lane = tid & 31;
    const int tg = lane >> 2;
    const int tq = lane & 3;
    const int warp_m = wid & 7;
    const int warp_n = wid >> 3;

    load_Bperm(Bpu, w, tid, 512);
    if (tid < H_DIM) bs[tid] = b[tid];

    const int n0 = blockIdx.x * 128;
    {
        const int c  = tid & 127;
        const int r0 = (tid >> 7) * 32;
        for (int i = 0; i < 32; i++) {
            int r = r0 + i;
            int idx = n0 + r; if (idx >= n_nodes) idx = n_nodes - 1;
            Au[r * SA + c] = f2tf32(in_feat[(size_t)idx * H_DIM + c]);
        }
    }
    __syncthreads();

    float cfr[8][4];
#pragma unroll
    for (int nt = 0; nt < 8; nt++)
#pragma unroll
        for (int q = 0; q < 4; q++) cfr[nt][q] = 0.f;

    const int rm = warp_m * 16;
#pragma unroll 4
    for (int kc = 0; kc < 16; kc++) {
        const int k0 = kc * 8;
        uint32_t afr[4];
        afr[0] = Au[(rm + tg) * SA + k0 + tq];
        afr[1] = Au[(rm + tg + 8) * SA + k0 + tq];
        afr[2] = Au[(rm + tg) * SA + k0 + tq + 4];
        afr[3] = Au[(rm + tg + 8) * SA + k0 + tq + 4];
        const uint4* bp = (const uint4*)(Bpu + (((warp_n << 4) + kc) << 9) + (lane << 4));
        const uint4 q0 = bp[0], q1 = bp[1], q2 = bp[2], q3 = bp[3];
        mma_tf32(cfr[0], afr, q0.x, q0.y);
        mma_tf32(cfr[1], afr, q0.z, q0.w);
        mma_tf32(cfr[2], afr, q1.x, q1.y);
        mma_tf32(cfr[3], afr, q1.z, q1.w);
        mma_tf32(cfr[4], afr, q2.x, q2.y);
        mma_tf32(cfr[5], afr, q2.z, q2.w);
        mma_tf32(cfr[6], afr, q3.x, q3.y);
        mma_tf32(cfr[7], afr, q3.z, q3.w);
    }

    // epilogue: bias + relu + direct STG
#pragma unroll
    for (int nt = 0; nt < 8; nt++) {
        const int cc = warp_n * 64 + nt * 8 + 2 * tq;
        const float2 bv = make_float2(bs[cc], bs[cc + 1]);
        const int nd0 = n0 + rm + tg;
        if (nd0 < n_nodes)
            *(float2*)(out + (size_t)nd0 * H_DIM + cc) =
                make_float2(fmaxf(cfr[nt][0] + bv.x, 0.f),
                            fmaxf(cfr[nt][1] + bv.y, 0.f));
        const int nd1 = nd0 + 8;
        if (nd1 < n_nodes)
            *(float2*)(out + (size_t)nd1 * H_DIM + cc) =
                make_float2(fmaxf(cfr[nt][2] + bv.x, 0.f),
                            fmaxf(cfr[nt][3] + bv.y, 0.f));
    }
}

// ---------------- edge scatter (segment_sum via vector RED) -----------------
__global__ void scatter_kernel(const int* __restrict__ src_idx,
                               const int* __restrict__ dst_idx, int n_edges,
                               const float* __restrict__ feat,
                               float* __restrict__ agg, float* __restrict__ deg)
{
    const int warp = (blockIdx.x * blockDim.x + threadIdx.x) >> 5;
    const int lane = threadIdx.x & 31;
    if (warp >= n_edges) return;
    const int s = src_idx[warp];
    const int d = dst_idx[warp];
    const float4 v = ((const float4*)(feat + (size_t)s * H_DIM))[lane];
    float4* a = ((float4*)(agg + (size_t)d * H_DIM)) + lane;
    asm volatile("red.global.add.v4.f32 [%0], {%1,%2,%3,%4};"
                 :: "l"(a), "f"(v.x), "f"(v.y), "f"(v.z), "f"(v.w) : "memory");
    if (lane == 0) atomicAdd(deg + d, 1.0f);
}

// ---------------- edge GNN node MLP: 8-node register-blocked GEMM -----------
#define GNN_NB 8
#define GNN_SMEM_FLOATS (2*H_DIM*H_DIM + H_DIM*H_DIM + 2*H_DIM + 2*H_DIM*GNN_NB + H_DIM*GNN_NB)
#define GNN_SMEM_BYTES  (GNN_SMEM_FLOATS * 4)

__global__ void __launch_bounds__(128, 1)
gnn_kernel(const float* __restrict__ node_in,
           const float* __restrict__ agg, const float* __restrict__ deg,
           const float* __restrict__ w1, const float* __restrict__ b1,
           const float* __restrict__ w2, const float* __restrict__ b2,
           float* __restrict__ out, int n_nodes, int nodes_per_block)
{
    extern __shared__ float smem[];
    float* w1s  = smem;
    float* w2s  = w1s + 2 * H_DIM * H_DIM;
    float* b1s  = w2s + H_DIM * H_DIM;
    float* b2s  = b1s + H_DIM;
    float* insT = b2s + H_DIM;
    float* hT   = insT + 2 * H_DIM * GNN_NB;

    const int tid = threadIdx.x;
    for (int i = tid; i < 2 * H_DIM * H_DIM; i += 128) w1s[i] = w1[i];
    for (int i = tid; i < H_DIM * H_DIM; i += 128) w2s[i] = w2[i];
    if (tid < H_DIM) { b1s[tid] = b1[tid]; b2s[tid] = b2[tid]; }
    __syncthreads();

    const float b1v = b1s[tid];
    const float b2v = b2s[tid];

    const int node0 = blockIdx.x * nodes_per_block;
    int node1 = node0 + nodes_per_block;
    if (node1 > n_nodes) node1 = n_nodes;

    const int jld = tid >> 4;
    const int lld = tid & 15;

    for (int g = node0; g < node1; g += GNN_NB) {
        {
            int nd = g + jld;
            if (nd >= n_nodes) nd = n_nodes - 1;
            const float invd = 1.0f / fmaxf(deg[nd], 1.0f);
            const float* np = node_in + (size_t)nd * H_DIM;
            const float* ap = agg + (size_t)nd * H_DIM;
#pragma unroll
            for (int r = 0; r < 8; r++) {
                const int k = lld + 16 * r;
                insT[k * GNN_NB + jld] = np[k];
                insT[(H_DIM + k) * GNN_NB + jld] = ap[k] * invd;
            }
        }
        __syncthreads();

        unsigned long long acc[4];
        {
            const unsigned long long bp = pack_dup(b1v);
#pragma unroll
            for (int j = 0; j < 4; j++) acc[j] = bp;
        }
#pragma unroll 4
        for (int k = 0; k < 2 * H_DIM; k++) {
            const unsigned long long wp = pack_dup(w1s[k * H_DIM + tid]);
            const ulonglong2* ip = ((const ulonglong2*)insT) + k * 2;
            const ulonglong2 a = ip[0];
            const ulonglong2 b = ip[1];
            ffma2(acc[0], a.x, wp);
            ffma2(acc[1], a.y, wp);
            ffma2(acc[2], b.x, wp);
            ffma2(acc[3], b.y, wp);
        }
        {
            const float2 v0 = unpack2(acc[0]);
            const float2 v1 = unpack2(acc[1]);
            const float2 v2 = unpack2(acc[2]);
            const float2 v3 = unpack2(acc[3]);
            float4* hp = (float4*)(hT + tid * GNN_NB);
            hp[0] = make_float4(fmaxf(v0.x, 0.f), fmaxf(v0.y, 0.f),
                                fmaxf(v1.x, 0.f), fmaxf(v1.y, 0.f));
            hp[1] = make_float4(fmaxf(v2.x, 0.f), fmaxf(v2.y, 0.f),
                                fmaxf(v3.x, 0.f), fmaxf(v3.y, 0.f));
        }
        __syncthreads();

        {
            const unsigned long long bp = pack_dup(b2v);
#pragma unroll
            for (int j = 0; j < 4; j++) acc[j] = bp;
        }
#pragma unroll 4
        for (int k = 0; k < H_DIM; k++) {
            const unsigned long long wp = pack_dup(w2s[k * H_DIM + tid]);
            const ulonglong2* hp = ((const ulonglong2*)hT) + k * 2;
            const ulonglong2 a = hp[0];
            const ulonglong2 b = hp[1];
            ffma2(acc[0], a.x, wp);
            ffma2(acc[1], a.y, wp);
            ffma2(acc[2], b.x, wp);
            ffma2(acc[3], b.y, wp);
        }

        float o[GNN_NB];
        {
            const float2 v0 = unpack2(acc[0]);
            const float2 v1 = unpack2(acc[1]);
            const float2 v2 = unpack2(acc[2]);
            const float2 v3 = unpack2(acc[3]);
            o[0] = fmaxf(v0.x, 0.f); o[1] = fmaxf(v0.y, 0.f);
            o[2] = fmaxf(v1.x, 0.f); o[3] = fmaxf(v1.y, 0.f);
            o[4] = fmaxf(v2.x, 0.f); o[5] = fmaxf(v2.y, 0.f);
            o[6] = fmaxf(v3.x, 0.f); o[7] = fmaxf(v3.y, 0.f);
        }
#pragma unroll
        for (int j = 0; j < GNN_NB; j++) {
            const int nd = g + j;
            if (nd < n_nodes) {
                const float nv = insT[tid * GNN_NB + j];
                out[(size_t)nd * H_DIM + tid] = nv + o[j];
            }
        }
        __syncthreads();
    }
}

// ---------------- launch -----------------------------------------------------
extern "C" void kernel_launch(void* const* d_in, const int* in_sizes, int n_in,
                              void* d_out, int out_size)
{
    const float* lane_points   = (const float*)d_in[0];
    const float* agent_history = (const float*)d_in[1];
    const int* e_ll = (const int*)d_in[2];
    const int* e_aa = (const int*)d_in[3];
    const int* e_la = (const int*)d_in[4];
    const float* lw1 = (const float*)d_in[5];
    const float* lb1 = (const float*)d_in[6];
    const float* lw2 = (const float*)d_in[7];
    const float* lb2 = (const float*)d_in[8];
    const float* lw3 = (const float*)d_in[9];
    const float* lb3 = (const float*)d_in[10];
    const float* aw1 = (const float*)d_in[11];
    const float* ab1 = (const float*)d_in[12];
    const float* aw2 = (const float*)d_in[13];
    const float* ab2 = (const float*)d_in[14];
    const float* aw3 = (const float*)d_in[15];
    const float* ab3 = (const float*)d_in[16];
    const float* ll_w1 = (const float*)d_in[17];
    const float* ll_b1 = (const float*)d_in[18];
    const float* ll_w2 = (const float*)d_in[19];
    const float* ll_b2 = (const float*)d_in[20];
    const float* aa_w1 = (const float*)d_in[21];
    const float* aa_b1 = (const float*)d_in[22];
    const float* aa_w2 = (const float*)d_in[23];
    const float* aa_b2 = (const float*)d_in[24];
    const float* la_w1 = (const float*)d_in[25];
    const float* la_b1 = (const float*)d_in[26];
    const float* la_w2 = (const float*)d_in[27];
    const float* la_b2 = (const float*)d_in[28];

    float* out = (float*)d_out;
    float* lane_out  = out;
    float* agent_out = out + (size_t)N_LANE * H_DIM;

    float *p_lane_enc, *p_agent_enc, *p_lane_agg, *p_agent_agg, *p_ms, *p_deg_l, *p_deg_a;
    cudaGetSymbolAddress((void**)&p_lane_enc,  g_lane_enc);
    cudaGetSymbolAddress((void**)&p_agent_enc, g_agent_enc);
    cudaGetSymbolAddress((void**)&p_lane_agg,  g_lane_agg);
    cudaGetSymbolAddress((void**)&p_agent_agg, g_agent_agg);
    cudaGetSymbolAddress((void**)&p_ms,        g_ms);
    cudaGetSymbolAddress((void**)&p_deg_l,     g_deg_l);
    cudaGetSymbolAddress((void**)&p_deg_a,     g_deg_a);

    cudaFuncSetAttribute(enc_mma_kernel, cudaFuncAttributeMaxDynamicSharedMemorySize, ENC3_SMEM_BYTES);
    cudaFuncSetAttribute(mlp_mma_kernel, cudaFuncAttributeMaxDynamicSharedMemorySize, MLP2_SMEM_BYTES);
    cudaFuncSetAttribute(gnn_kernel,     cudaFuncAttributeMaxDynamicSharedMemorySize, GNN_SMEM_BYTES);

    const int agent_tiles = (N_AGENT + ENC_TILE_NODES - 1) / ENC_TILE_NODES;
    const int lane_tiles  = (N_LANE + ENC_TILE_NODES - 1) / ENC_TILE_NODES;

    zero_all_kernel<<<2048, 256>>>();
    enc_mma_kernel<<<148, 512, ENC3_SMEM_BYTES>>>(
        agent_history, aw1, ab1, aw2, ab2, p_ms, N_AGENT, agent_tiles);
    mlp_mma_kernel<<<(N_AGENT + 127) / 128, 512, MLP2_SMEM_BYTES>>>(
        p_ms, aw3, ab3, p_agent_enc, N_AGENT);
    enc_mma_kernel<<<148, 512, ENC3_SMEM_BYTES>>>(
        lane_points, lw1, lb1, lw2, lb2, p_ms, N_LANE, lane_tiles);
    mlp_mma_kernel<<<(N_LANE + 127) / 128, 512, MLP2_SMEM_BYTES>>>(
        p_ms, lw3, lb3, p_lane_enc, N_LANE);

    scatter_kernel<<<(E_LL + 7) / 8, 256>>>(e_ll, e_ll + E_LL, E_LL,
                                            p_lane_enc, p_lane_agg, p_deg_l);
    gnn_kernel<<<(N_LANE + 71) / 72, 128, GNN_SMEM_BYTES>>>(
        p_lane_enc, p_lane_agg, p_deg_l, ll_w1, ll_b1, ll_w2, ll_b2,
        lane_out, N_LANE, 72);

    scatter_kernel<<<(E_AA + 7) / 8, 256>>>(e_aa, e_aa + E_AA, E_AA,
                                            p_agent_enc, p_agent_agg, p_deg_a);
    gnn_kernel<<<(N_AGENT + 31) / 32, 128, GNN_SMEM_BYTES>>>(
        p_agent_enc, p_agent_agg, p_deg_a, aa_w1, aa_b1, aa_w2, aa_b2,
        agent_out, N_AGENT, 32);

    zero_agent_kernel<<<1024, 256>>>();
    scatter_kernel<<<(E_LA + 7) / 8, 256>>>(e_la, e_la + E_LA, E_LA,
                                            lane_out, p_agent_agg, p_deg_a);
    gnn_kernel<<<(N_AGENT + 31) / 32, 128, GNN_SMEM_BYTES>>>(
        agent_out, p_agent_agg, p_deg_a, la_w1, la_b1, la_w2, la_b2,
        agent_out, N_AGENT, 32);
}

// round 6
// speedup vs baseline: 1.3089x; 1.3089x over previous
#include <cuda_runtime.h>
#include <cstddef>
#include <cstdint>

#define N_LANE  20000
#define P_LANE  20
#define N_AGENT 4000
#define T_AGENT 20
#define F_DIM   8
#define H_DIM   128
#define E_LL    640000
#define E_AA    128000
#define E_LA    200000

// ---------------- scratch (device globals; no allocation allowed) -----------
__device__ float g_lane_enc [N_LANE  * H_DIM];
__device__ float g_agent_enc[N_AGENT * H_DIM];
__device__ float g_lane_agg [N_LANE  * H_DIM];
__device__ float g_agent_agg[N_AGENT * H_DIM];
__device__ float g_ms      [N_LANE  * H_DIM];
__device__ float g_deg_l[N_LANE];
__device__ float g_deg_a[N_AGENT];

// ---------------- tf32 mma.sync helpers --------------------------------------
__device__ __forceinline__ uint32_t f2tf32(float f) {
    uint32_t u;
    asm("cvt.rna.tf32.f32 %0, %1;" : "=r"(u) : "f"(f));
    return u;
}
__device__ __forceinline__ void mma_tf32(float c[4], const uint32_t a[4],
                                         uint32_t b0, uint32_t b1) {
    asm("mma.sync.aligned.m16n8k8.row.col.f32.tf32.tf32.f32 "
        "{%0,%1,%2,%3}, {%4,%5,%6,%7}, {%8,%9}, {%0,%1,%2,%3};"
        : "+f"(c[0]), "+f"(c[1]), "+f"(c[2]), "+f"(c[3])
        : "r"(a[0]), "r"(a[1]), "r"(a[2]), "r"(a[3]), "r"(b0), "r"(b1));
}

// ---------------- packed f32x2 helpers (GNN path) ----------------------------
__device__ __forceinline__ void ffma2(unsigned long long& d,
                                      unsigned long long a,
                                      unsigned long long b) {
    asm("fma.rn.f32x2 %0, %1, %2, %0;" : "+l"(d) : "l"(a), "l"(b));
}
__device__ __forceinline__ unsigned long long pack_dup(float x) {
    unsigned long long r;
    unsigned u = __float_as_uint(x);
    asm("mov.b64 %0, {%1, %2};" : "=l"(r) : "r"(u), "r"(u));
    return r;
}
__device__ __forceinline__ float2 unpack2(unsigned long long v) {
    unsigned lo, hi;
    asm("mov.b64 {%0, %1}, %2;" : "=r"(lo), "=r"(hi) : "l"(v));
    return make_float2(__uint_as_float(lo), __uint_as_float(hi));
}

// ---------------- zero kernels ----------------------------------------------
__global__ void zero_all_kernel() {
    int i = blockIdx.x * blockDim.x + threadIdx.x;
    int stride = gridDim.x * blockDim.x;
    for (int k = i; k < N_LANE * H_DIM; k += stride) g_lane_agg[k] = 0.f;
    for (int k = i; k < N_AGENT * H_DIM; k += stride) g_agent_agg[k] = 0.f;
    for (int k = i; k < N_LANE; k += stride) g_deg_l[k] = 0.f;
    for (int k = i; k < N_AGENT; k += stride) g_deg_a[k] = 0.f;
}
__global__ void zero_agent_kernel() {
    int i = blockIdx.x * blockDim.x + threadIdx.x;
    int stride = gridDim.x * blockDim.x;
    for (int k = i; k < N_AGENT * H_DIM; k += stride) g_agent_agg[k] = 0.f;
    for (int k = i; k < N_AGENT; k += stride) g_deg_a[k] = 0.f;
}

// ---------------- shared Bperm init (quad-major, conflict-free LDS.128) ------
// Chunk (wn*16+kc) = 512 u32: [quad q][lane l][elem e];  reg = q*4+e,
// nt = reg>>1, p = reg&1 -> element (k = kc*8 + (l&3) + 4p, n = wn*64 + nt*8 + (l>>2))
__device__ __forceinline__ void load_Bperm(uint32_t* Bpu, const float* __restrict__ w,
                                           int tid, int nthreads) {
    for (int idx = tid; idx < 16384; idx += nthreads) {
        const int chunk = idx >> 9;
        const int q = (idx >> 7) & 3;
        const int l = (idx >> 2) & 31;
        const int e = idx & 3;
        const int kc = chunk & 15, wn = chunk >> 4;
        const int reg = q * 4 + e;
        const int nt = reg >> 1, p = reg & 1;
        const int k = kc * 8 + (l & 3) + 4 * p;
        const int n = wn * 64 + nt * 8 + (l >> 2);
        Bpu[idx] = f2tf32(w[k * H_DIM + n]);
    }
}

// ---------------- tensor encoder (stages 1+2+max), 512 threads ---------------
#define ENC_TILE_NODES 6
#define SA 132
#define ENC3_SMEM_FLOATS (16896 + 16384 + 960 + 1024 + 128 + 128 + 16)
#define ENC3_SMEM_BYTES  (ENC3_SMEM_FLOATS * 4)

__global__ void __launch_bounds__(512, 1)
enc_mma_kernel(const float* __restrict__ x_in,
               const float* __restrict__ w1, const float* __restrict__ b1,
               const float* __restrict__ w2, const float* __restrict__ b2,
               float* __restrict__ ms_out, int n_nodes, int n_tiles)
{
    extern __shared__ float smem[];
    float* A     = smem;               // tf32 bits during mma; f32 Dbuf after
    float* Bperm = A + 16896;          // 16384
    float* xs    = Bperm + 16384;
    float* w1s   = xs + 960;
    float* b1s   = w1s + 1024;
    float* b2s   = b1s + 128;
    float* refv  = b2s + 128;

    uint32_t* Au  = (uint32_t*)A;
    uint32_t* Bpu = (uint32_t*)Bperm;

    const int tid  = threadIdx.x;      // 0..511
    const int wid  = tid >> 5;         // 0..15
    const int lane = tid & 31;
    const int tg = lane >> 2;
    const int tq = lane & 3;
    const int warp_m = wid & 7;        // 8 x 16-row tiles
    const int warp_n = wid >> 3;       // 2 x 64-col tiles

    load_Bperm(Bpu, w2, tid, 512);
    for (int i = tid; i < F_DIM * H_DIM; i += 512) w1s[i] = w1[i];
    if (tid < H_DIM) { b1s[tid] = b1[tid]; b2s[tid] = b2[tid]; }
    __syncthreads();

    const int c    = tid & 127;
    const int rgrp = tid >> 7;         // 0..3, 30 rows each
    float wa[F_DIM];
#pragma unroll
    for (int f = 0; f < F_DIM; f++) wa[f] = w1s[f * H_DIM + c];
    const float b1v = b1s[c];

    for (int tile = blockIdx.x; tile < n_tiles; tile += gridDim.x) {
        const int node0 = tile * ENC_TILE_NODES;

        // ---- load x (6 nodes x 160), clamped ----
        for (int i = tid; i < ENC_TILE_NODES * P_LANE * F_DIM; i += 512) {
            int j = i / (P_LANE * F_DIM);
            int nd = node0 + j; if (nd >= n_nodes) nd = n_nodes - 1;
            xs[i] = x_in[(size_t)nd * (P_LANE * F_DIM) + (i - j * (P_LANE * F_DIM))];
        }
        __syncthreads();
        if (tid < 2 * ENC_TILE_NODES)
            refv[tid] = xs[(tid >> 1) * 160 + 19 * 8 + (tid & 1)];
        __syncthreads();
        if (tid < 240) {
            int j = tid / 40, rem = tid % 40, t = rem >> 1, f = rem & 1;
            xs[j * 160 + t * 8 + f] -= refv[j * 2 + f];
        }
        __syncthreads();

        // ---- stage 1: A(r,c) = tf32(relu(b1 + x'[r].w1[:,c])), rows 0..119 ----
#pragma unroll 3
        for (int i = 0; i < 30; i++) {
            const int r = rgrp * 30 + i;
            const float4* xp = (const float4*)(xs + r * 8);
            const float4 x0 = xp[0], x1 = xp[1];
            float s = b1v;
            s = fmaf(x0.x, wa[0], s); s = fmaf(x0.y, wa[1], s);
            s = fmaf(x0.z, wa[2], s); s = fmaf(x0.w, wa[3], s);
            s = fmaf(x1.x, wa[4], s); s = fmaf(x1.y, wa[5], s);
            s = fmaf(x1.z, wa[6], s); s = fmaf(x1.w, wa[7], s);
            Au[r * SA + c] = f2tf32(fmaxf(s, 0.f));
        }
        // zero pad rows 120..127
        for (int i = tid; i < 8 * 128; i += 512)
            Au[(120 + (i >> 7)) * SA + (i & 127)] = 0;
        __syncthreads();

        // ---- mma: D[128x128] = A @ B, warp tile 16x64 ----
        float cfr[8][4];
#pragma unroll
        for (int nt = 0; nt < 8; nt++)
#pragma unroll
            for (int q = 0; q < 4; q++) cfr[nt][q] = 0.f;

        const int rm = warp_m * 16;
#pragma unroll 4
        for (int kc = 0; kc < 16; kc++) {
            const int k0 = kc * 8;
            uint32_t afr[4];
            afr[0] = Au[(rm + tg) * SA + k0 + tq];
            afr[1] = Au[(rm + tg + 8) * SA + k0 + tq];
            afr[2] = Au[(rm + tg) * SA + k0 + tq + 4];
            afr[3] = Au[(rm + tg + 8) * SA + k0 + tq + 4];
            const uint4* bp = (const uint4*)(Bpu + (((warp_n << 4) + kc) << 9));
            const uint4 q0 = bp[0 * 32 + lane];
            const uint4 q1 = bp[1 * 32 + lane];
            const uint4 q2 = bp[2 * 32 + lane];
            const uint4 q3 = bp[3 * 32 + lane];
            mma_tf32(cfr[0], afr, q0.x, q0.y);
            mma_tf32(cfr[1], afr, q0.z, q0.w);
            mma_tf32(cfr[2], afr, q1.x, q1.y);
            mma_tf32(cfr[3], afr, q1.z, q1.w);
            mma_tf32(cfr[4], afr, q2.x, q2.y);
            mma_tf32(cfr[5], afr, q2.z, q2.w);
            mma_tf32(cfr[6], afr, q3.x, q3.y);
            mma_tf32(cfr[7], afr, q3.z, q3.w);
        }
        __syncthreads();   // all A reads done; A memory becomes Dbuf

        // ---- store C frags to Dbuf ----
        {
            const int rr = rm + tg;
#pragma unroll
            for (int nt = 0; nt < 8; nt++) {
                const int cc = warp_n * 64 + nt * 8 + 2 * tq;
                *(float2*)(A + rr * SA + cc)       = make_float2(cfr[nt][0], cfr[nt][1]);
                *(float2*)(A + (rr + 8) * SA + cc) = make_float2(cfr[nt][2], cfr[nt][3]);
            }
        }
        __syncthreads();

        // ---- per-node max over 20 rows + bias + relu -> g_ms ----
        for (int task = tid; task < ENC_TILE_NODES * H_DIM; task += 512) {
            const int j = task >> 7, cc = task & 127;
            const int nd = node0 + j;
            if (nd < n_nodes) {
                float m = -3.4e38f;
                const float* dp = A + (j * 20) * SA + cc;
#pragma unroll
                for (int r = 0; r < 20; r++) m = fmaxf(m, dp[r * SA]);
                ms_out[(size_t)nd * H_DIM + cc] = fmaxf(m + b2s[cc], 0.f);
            }
        }
        __syncthreads();
    }
}

// ---------------- tensor MLP: out = relu(in @ w + b), 128-row tiles ----------
#define MLP2_SMEM_FLOATS (16896 + 16384 + 128)
#define MLP2_SMEM_BYTES  (MLP2_SMEM_FLOATS * 4)

__global__ void __launch_bounds__(512, 1)
mlp_mma_kernel(const float* __restrict__ in_feat,
               const float* __restrict__ w, const float* __restrict__ b,
               float* __restrict__ out, int n_nodes)
{
    extern __shared__ float smem[];
    float* A     = smem;
    float* Bperm = A + 16896;
    float* bs    = Bperm + 16384;
    uint32_t* Au  = (uint32_t*)A;
    uint32_t* Bpu = (uint32_t*)Bperm;

    const int tid  = threadIdx.x;
    const int wid  = tid >> 5;
    const int lane = tid & 31;
    const int tg = lane >> 2;
    const int tq = lane & 3;
    const int warp_m = wid & 7;
    const int warp_n = wid >> 3;

    load_Bperm(Bpu, w, tid, 512);
    if (tid < H_DIM) bs[tid] = b[tid];

    const int n0 = blockIdx.x * 128;
    {
        const int c  = tid & 127;
        const int r0 = (tid >> 7) * 32;
        for (int i = 0; i < 32; i++) {
            int r = r0 + i;
            int idx = n0 + r; if (idx >= n_nodes) idx = n_nodes - 1;
            Au[r * SA + c] = f2tf32(in_feat[(size_t)idx * H_DIM + c]);
        }
    }
    __syncthreads();

    float cfr[8][4];
#pragma unroll
    for (int nt = 0; nt < 8; nt++)
#pragma unroll
        for (int q = 0; q < 4; q++) cfr[nt][q] = 0.f;

    const int rm = warp_m * 16;
#pragma unroll 4
    for (int kc = 0; kc < 16; kc++) {
        const int k0 = kc * 8;
        uint32_t afr[4];
        afr[0] = Au[(rm + tg) * SA + k0 + tq];
        afr[1] = Au[(rm + tg + 8) * SA + k0 + tq];
        afr[2] = Au[(rm + tg) * SA + k0 + tq + 4];
        afr[3] = Au[(rm + tg + 8) * SA + k0 + tq + 4];
        const uint4* bp = (const uint4*)(Bpu + (((warp_n << 4) + kc) << 9));
        const uint4 q0 = bp[0 * 32 + lane];
        const uint4 q1 = bp[1 * 32 + lane];
        const uint4 q2 = bp[2 * 32 + lane];
        const uint4 q3 = bp[3 * 32 + lane];
        mma_tf32(cfr[0], afr, q0.x, q0.y);
        mma_tf32(cfr[1], afr, q0.z, q0.w);
        mma_tf32(cfr[2], afr, q1.x, q1.y);
        mma_tf32(cfr[3], afr, q1.z, q1.w);
        mma_tf32(cfr[4], afr, q2.x, q2.y);
        mma_tf32(cfr[5], afr, q2.z, q2.w);
        mma_tf32(cfr[6], afr, q3.x, q3.y);
        mma_tf32(cfr[7], afr, q3.z, q3.w);
    }

    // epilogue: bias + relu + direct STG
#pragma unroll
    for (int nt = 0; nt < 8; nt++) {
        const int cc = warp_n * 64 + nt * 8 + 2 * tq;
        const float2 bv = make_float2(bs[cc], bs[cc + 1]);
        const int nd0 = n0 + rm + tg;
        if (nd0 < n_nodes)
            *(float2*)(out + (size_t)nd0 * H_DIM + cc) =
                make_float2(fmaxf(cfr[nt][0] + bv.x, 0.f),
                            fmaxf(cfr[nt][1] + bv.y, 0.f));
        const int nd1 = nd0 + 8;
        if (nd1 < n_nodes)
            *(float2*)(out + (size_t)nd1 * H_DIM + cc) =
                make_float2(fmaxf(cfr[nt][2] + bv.x, 0.f),
                            fmaxf(cfr[nt][3] + bv.y, 0.f));
    }
}

// ---------------- edge scatter (segment_sum via vector RED) -----------------
__global__ void scatter_kernel(const int* __restrict__ src_idx,
                               const int* __restrict__ dst_idx, int n_edges,
                               const float* __restrict__ feat,
                               float* __restrict__ agg, float* __restrict__ deg)
{
    const int warp = (blockIdx.x * blockDim.x + threadIdx.x) >> 5;
    const int lane = threadIdx.x & 31;
    if (warp >= n_edges) return;
    const int s = src_idx[warp];
    const int d = dst_idx[warp];
    const float4 v = ((const float4*)(feat + (size_t)s * H_DIM))[lane];
    float4* a = ((float4*)(agg + (size_t)d * H_DIM)) + lane;
    asm volatile("red.global.add.v4.f32 [%0], {%1,%2,%3,%4};"
                 :: "l"(a), "f"(v.x), "f"(v.y), "f"(v.z), "f"(v.w) : "memory");
    if (lane == 0) atomicAdd(deg + d, 1.0f);
}

// ---------------- edge GNN node MLP: 8-node register-blocked GEMM -----------
#define GNN_NB 8
#define GNN_SMEM_FLOATS (2*H_DIM*H_DIM + H_DIM*H_DIM + 2*H_DIM + 2*H_DIM*GNN_NB + H_DIM*GNN_NB)
#define GNN_SMEM_BYTES  (GNN_SMEM_FLOATS * 4)

__global__ void __launch_bounds__(128, 1)
gnn_kernel(const float* __restrict__ node_in,
           const float* __restrict__ agg, const float* __restrict__ deg,
           const float* __restrict__ w1, const float* __restrict__ b1,
           const float* __restrict__ w2, const float* __restrict__ b2,
           float* __restrict__ out, int n_nodes, int nodes_per_block)
{
    extern __shared__ float smem[];
    float* w1s  = smem;
    float* w2s  = w1s + 2 * H_DIM * H_DIM;
    float* b1s  = w2s + H_DIM * H_DIM;
    float* b2s  = b1s + H_DIM;
    float* insT = b2s + H_DIM;
    float* hT   = insT + 2 * H_DIM * GNN_NB;

    const int tid = threadIdx.x;
    for (int i = tid; i < 2 * H_DIM * H_DIM; i += 128) w1s[i] = w1[i];
    for (int i = tid; i < H_DIM * H_DIM; i += 128) w2s[i] = w2[i];
    if (tid < H_DIM) { b1s[tid] = b1[tid]; b2s[tid] = b2[tid]; }
    __syncthreads();

    const float b1v = b1s[tid];
    const float b2v = b2s[tid];

    const int node0 = blockIdx.x * nodes_per_block;
    int node1 = node0 + nodes_per_block;
    if (node1 > n_nodes) node1 = n_nodes;

    const int jld = tid >> 4;
    const int lld = tid & 15;

    for (int g = node0; g < node1; g += GNN_NB) {
        {
            int nd = g + jld;
            if (nd >= n_nodes) nd = n_nodes - 1;
            const float invd = 1.0f / fmaxf(deg[nd], 1.0f);
            const float* np = node_in + (size_t)nd * H_DIM;
            const float* ap = agg + (size_t)nd * H_DIM;
#pragma unroll
            for (int r = 0; r < 8; r++) {
                const int k = lld + 16 * r;
                insT[k * GNN_NB + jld] = np[k];
                insT[(H_DIM + k) * GNN_NB + jld] = ap[k] * invd;
            }
        }
        __syncthreads();

        unsigned long long acc[4];
        {
            const unsigned long long bp = pack_dup(b1v);
#pragma unroll
            for (int j = 0; j < 4; j++) acc[j] = bp;
        }
#pragma unroll 4
        for (int k = 0; k < 2 * H_DIM; k++) {
            const unsigned long long wp = pack_dup(w1s[k * H_DIM + tid]);
            const ulonglong2* ip = ((const ulonglong2*)insT) + k * 2;
            const ulonglong2 a = ip[0];
            const ulonglong2 b = ip[1];
            ffma2(acc[0], a.x, wp);
            ffma2(acc[1], a.y, wp);
            ffma2(acc[2], b.x, wp);
            ffma2(acc[3], b.y, wp);
        }
        {
            const float2 v0 = unpack2(acc[0]);
            const float2 v1 = unpack2(acc[1]);
            const float2 v2 = unpack2(acc[2]);
            const float2 v3 = unpack2(acc[3]);
            float4* hp = (float4*)(hT + tid * GNN_NB);
            hp[0] = make_float4(fmaxf(v0.x, 0.f), fmaxf(v0.y, 0.f),
                                fmaxf(v1.x, 0.f), fmaxf(v1.y, 0.f));
            hp[1] = make_float4(fmaxf(v2.x, 0.f), fmaxf(v2.y, 0.f),
                                fmaxf(v3.x, 0.f), fmaxf(v3.y, 0.f));
        }
        __syncthreads();

        {
            const unsigned long long bp = pack_dup(b2v);
#pragma unroll
            for (int j = 0; j < 4; j++) acc[j] = bp;
        }
#pragma unroll 4
        for (int k = 0; k < H_DIM; k++) {
            const unsigned long long wp = pack_dup(w2s[k * H_DIM + tid]);
            const ulonglong2* hp = ((const ulonglong2*)hT) + k * 2;
            const ulonglong2 a = hp[0];
            const ulonglong2 b = hp[1];
            ffma2(acc[0], a.x, wp);
            ffma2(acc[1], a.y, wp);
            ffma2(acc[2], b.x, wp);
            ffma2(acc[3], b.y, wp);
        }

        float o[GNN_NB];
        {
            const float2 v0 = unpack2(acc[0]);
            const float2 v1 = unpack2(acc[1]);
            const float2 v2 = unpack2(acc[2]);
            const float2 v3 = unpack2(acc[3]);
            o[0] = fmaxf(v0.x, 0.f); o[1] = fmaxf(v0.y, 0.f);
            o[2] = fmaxf(v1.x, 0.f); o[3] = fmaxf(v1.y, 0.f);
            o[4] = fmaxf(v2.x, 0.f); o[5] = fmaxf(v2.y, 0.f);
            o[6] = fmaxf(v3.x, 0.f); o[7] = fmaxf(v3.y, 0.f);
        }
#pragma unroll
        for (int j = 0; j < GNN_NB; j++) {
            const int nd = g + j;
            if (nd < n_nodes) {
                const float nv = insT[tid * GNN_NB + j];
                out[(size_t)nd * H_DIM + tid] = nv + o[j];
            }
        }
        __syncthreads();
    }
}

// ---------------- launch -----------------------------------------------------
extern "C" void kernel_launch(void* const* d_in, const int* in_sizes, int n_in,
                              void* d_out, int out_size)
{
    const float* lane_points   = (const float*)d_in[0];
    const float* agent_history = (const float*)d_in[1];
    const int* e_ll = (const int*)d_in[2];
    const int* e_aa = (const int*)d_in[3];
    const int* e_la = (const int*)d_in[4];
    const float* lw1 = (const float*)d_in[5];
    const float* lb1 = (const float*)d_in[6];
    const float* lw2 = (const float*)d_in[7];
    const float* lb2 = (const float*)d_in[8];
    const float* lw3 = (const float*)d_in[9];
    const float* lb3 = (const float*)d_in[10];
    const float* aw1 = (const float*)d_in[11];
    const float* ab1 = (const float*)d_in[12];
    const float* aw2 = (const float*)d_in[13];
    const float* ab2 = (const float*)d_in[14];
    const float* aw3 = (const float*)d_in[15];
    const float* ab3 = (const float*)d_in[16];
    const float* ll_w1 = (const float*)d_in[17];
    const float* ll_b1 = (const float*)d_in[18];
    const float* ll_w2 = (const float*)d_in[19];
    const float* ll_b2 = (const float*)d_in[20];
    const float* aa_w1 = (const float*)d_in[21];
    const float* aa_b1 = (const float*)d_in[22];
    const float* aa_w2 = (const float*)d_in[23];
    const float* aa_b2 = (const float*)d_in[24];
    const float* la_w1 = (const float*)d_in[25];
    const float* la_b1 = (const float*)d_in[26];
    const float* la_w2 = (const float*)d_in[27];
    const float* la_b2 = (const float*)d_in[28];

    float* out = (float*)d_out;
    float* lane_out  = out;
    float* agent_out = out + (size_t)N_LANE * H_DIM;

    float *p_lane_enc, *p_agent_enc, *p_lane_agg, *p_agent_agg, *p_ms, *p_deg_l, *p_deg_a;
    cudaGetSymbolAddress((void**)&p_lane_enc,  g_lane_enc);
    cudaGetSymbolAddress((void**)&p_agent_enc, g_agent_enc);
    cudaGetSymbolAddress((void**)&p_lane_agg,  g_lane_agg);
    cudaGetSymbolAddress((void**)&p_agent_agg, g_agent_agg);
    cudaGetSymbolAddress((void**)&p_ms,        g_ms);
    cudaGetSymbolAddress((void**)&p_deg_l,     g_deg_l);
    cudaGetSymbolAddress((void**)&p_deg_a,     g_deg_a);

    cudaFuncSetAttribute(enc_mma_kernel, cudaFuncAttributeMaxDynamicSharedMemorySize, ENC3_SMEM_BYTES);
    cudaFuncSetAttribute(mlp_mma_kernel, cudaFuncAttributeMaxDynamicSharedMemorySize, MLP2_SMEM_BYTES);
    cudaFuncSetAttribute(gnn_kernel,     cudaFuncAttributeMaxDynamicSharedMemorySize, GNN_SMEM_BYTES);

    const int agent_tiles = (N_AGENT + ENC_TILE_NODES - 1) / ENC_TILE_NODES;
    const int lane_tiles  = (N_LANE + ENC_TILE_NODES - 1) / ENC_TILE_NODES;

    zero_all_kernel<<<2048, 256>>>();
    enc_mma_kernel<<<148, 512, ENC3_SMEM_BYTES>>>(
        agent_history, aw1, ab1, aw2, ab2, p_ms, N_AGENT, agent_tiles);
    mlp_mma_kernel<<<(N_AGENT + 127) / 128, 512, MLP2_SMEM_BYTES>>>(
        p_ms, aw3, ab3, p_agent_enc, N_AGENT);
    enc_mma_kernel<<<148, 512, ENC3_SMEM_BYTES>>>(
        lane_points, lw1, lb1, lw2, lb2, p_ms, N_LANE, lane_tiles);
    mlp_mma_kernel<<<(N_LANE + 127) / 128, 512, MLP2_SMEM_BYTES>>>(
        p_ms, lw3, lb3, p_lane_enc, N_LANE);

    scatter_kernel<<<(E_LL + 7) / 8, 256>>>(e_ll, e_ll + E_LL, E_LL,
                                            p_lane_enc, p_lane_agg, p_deg_l);
    gnn_kernel<<<(N_LANE + 71) / 72, 128, GNN_SMEM_BYTES>>>(
        p_lane_enc, p_lane_agg, p_deg_l, ll_w1, ll_b1, ll_w2, ll_b2,
        lane_out, N_LANE, 72);

    scatter_kernel<<<(E_AA + 7) / 8, 256>>>(e_aa, e_aa + E_AA, E_AA,
                                            p_agent_enc, p_agent_agg, p_deg_a);
    gnn_kernel<<<(N_AGENT + 31) / 32, 128, GNN_SMEM_BYTES>>>(
        p_agent_enc, p_agent_agg, p_deg_a, aa_w1, aa_b1, aa_w2, aa_b2,
        agent_out, N_AGENT, 32);

    zero_agent_kernel<<<1024, 256>>>();
    scatter_kernel<<<(E_LA + 7) / 8, 256>>>(e_la, e_la + E_LA, E_LA,
                                            lane_out, p_agent_agg, p_deg_a);
    gnn_kernel<<<(N_AGENT + 31) / 32, 128, GNN_SMEM_BYTES>>>(
        agent_out, p_agent_agg, p_deg_a, la_w1, la_b1, la_w2, la_b2,
        agent_out, N_AGENT, 32);
}

// round 7
// speedup vs baseline: 1.3571x; 1.0368x over previous
#include <cuda_runtime.h>
#include <cstddef>
#include <cstdint>

#define N_LANE  20000
#define P_LANE  20
#define N_AGENT 4000
#define T_AGENT 20
#define F_DIM   8
#define H_DIM   128
#define E_LL    640000
#define E_AA    128000
#define E_LA    200000

// ---------------- scratch (device globals; no allocation allowed) -----------
__device__ float g_lane_enc [N_LANE  * H_DIM];
__device__ float g_agent_enc[N_AGENT * H_DIM];
__device__ float g_lane_agg [N_LANE  * H_DIM];
__device__ float g_agent_agg[N_AGENT * H_DIM];
__device__ float g_ms      [N_LANE  * H_DIM];
__device__ float g_deg_l[N_LANE];
__device__ float g_deg_a[N_AGENT];

// ---------------- tf32 mma.sync helpers --------------------------------------
__device__ __forceinline__ uint32_t f2tf32(float f) {
    uint32_t u;
    asm("cvt.rna.tf32.f32 %0, %1;" : "=r"(u) : "f"(f));
    return u;
}
__device__ __forceinline__ void mma_tf32(float c[4], const uint32_t a[4],
                                         uint32_t b0, uint32_t b1) {
    asm("mma.sync.aligned.m16n8k8.row.col.f32.tf32.tf32.f32 "
        "{%0,%1,%2,%3}, {%4,%5,%6,%7}, {%8,%9}, {%0,%1,%2,%3};"
        : "+f"(c[0]), "+f"(c[1]), "+f"(c[2]), "+f"(c[3])
        : "r"(a[0]), "r"(a[1]), "r"(a[2]), "r"(a[3]), "r"(b0), "r"(b1));
}

// ---------------- packed f32x2 helpers (GNN path) ----------------------------
__device__ __forceinline__ void ffma2(unsigned long long& d,
                                      unsigned long long a,
                                      unsigned long long b) {
    asm("fma.rn.f32x2 %0, %1, %2, %0;" : "+l"(d) : "l"(a), "l"(b));
}
__device__ __forceinline__ unsigned long long pack_dup(float x) {
    unsigned long long r;
    unsigned u = __float_as_uint(x);
    asm("mov.b64 %0, {%1, %2};" : "=l"(r) : "r"(u), "r"(u));
    return r;
}
__device__ __forceinline__ float2 unpack2(unsigned long long v) {
    unsigned lo, hi;
    asm("mov.b64 {%0, %1}, %2;" : "=r"(lo), "=r"(hi) : "l"(v));
    return make_float2(__uint_as_float(lo), __uint_as_float(hi));
}

// ---------------- zero kernels ----------------------------------------------
__global__ void zero_all_kernel() {
    int i = blockIdx.x * blockDim.x + threadIdx.x;
    int stride = gridDim.x * blockDim.x;
    for (int k = i; k < N_LANE * H_DIM; k += stride) g_lane_agg[k] = 0.f;
    for (int k = i; k < N_AGENT * H_DIM; k += stride) g_agent_agg[k] = 0.f;
    for (int k = i; k < N_LANE; k += stride) g_deg_l[k] = 0.f;
    for (int k = i; k < N_AGENT; k += stride) g_deg_a[k] = 0.f;
}
__global__ void zero_agent_kernel() {
    int i = blockIdx.x * blockDim.x + threadIdx.x;
    int stride = gridDim.x * blockDim.x;
    for (int k = i; k < N_AGENT * H_DIM; k += stride) g_agent_agg[k] = 0.f;
    for (int k = i; k < N_AGENT; k += stride) g_deg_a[k] = 0.f;
}

// ---------------- shared Bperm init (quad-major, 32-col n-groups) ------------
// Chunk (ng*16+kc) = 256 u32: [q 0..1][lane 0..31][e 0..3]; re = q*4+e,
// nt = re>>1, p = re&1 -> element (k = kc*8 + (l&3) + 4p, n = ng*32 + nt*8 + (l>>2))
__device__ __forceinline__ void load_Bperm(uint32_t* Bpu, const float* __restrict__ w,
                                           int tid, int nthreads) {
    for (int idx = tid; idx < 16384; idx += nthreads) {
        const int chunk = idx >> 8;            // 0..63
        const int q = (idx >> 7) & 1;
        const int l = (idx >> 2) & 31;
        const int e = idx & 3;
        const int kc = chunk & 15, ng = chunk >> 4;
        const int re = q * 4 + e;
        const int nt = re >> 1, p = re & 1;
        const int k = kc * 8 + (l & 3) + 4 * p;
        const int n = ng * 32 + nt * 8 + (l >> 2);
        Bpu[idx] = f2tf32(w[k * H_DIM + n]);
    }
}

// ---------------- tensor encoder (stages 1+2+max), 512 threads ---------------
#define ENC_TILE_NODES 6
#define SA 132
#define ENC3_SMEM_FLOATS (16896 + 16384 + 960 + 1024 + 128 + 128 + 16)
#define ENC3_SMEM_BYTES  (ENC3_SMEM_FLOATS * 4)

__global__ void __launch_bounds__(512, 1)
enc_mma_kernel(const float* __restrict__ x_in,
               const float* __restrict__ w1, const float* __restrict__ b1,
               const float* __restrict__ w2, const float* __restrict__ b2,
               float* __restrict__ ms_out, int n_nodes, int n_tiles)
{
    extern __shared__ float smem[];
    float* A     = smem;               // tf32 bits during mma; f32 Dbuf after
    float* Bperm = A + 16896;          // 16384
    float* xs    = Bperm + 16384;
    float* w1s   = xs + 960;
    float* b1s   = w1s + 1024;
    float* b2s   = b1s + 128;
    float* refv  = b2s + 128;

    uint32_t* Au  = (uint32_t*)A;
    uint32_t* Bpu = (uint32_t*)Bperm;

    const int tid  = threadIdx.x;      // 0..511
    const int wid  = tid >> 5;         // 0..15
    const int lane = tid & 31;
    const int tg = lane >> 2;
    const int tq = lane & 3;
    const int warp_m = wid & 3;        // 4 x 32-row groups
    const int warp_n = wid >> 2;       // 4 x 32-col groups
    const int rm = warp_m * 32;

    load_Bperm(Bpu, w2, tid, 512);
    for (int i = tid; i < F_DIM * H_DIM; i += 512) w1s[i] = w1[i];
    if (tid < H_DIM) { b1s[tid] = b1[tid]; b2s[tid] = b2[tid]; }
    // zero pad rows 120..127 ONCE (C-stores below never touch them)
    for (int i = tid; i < 8 * SA; i += 512)
        Au[120 * SA + i] = 0;
    __syncthreads();

    const int c    = tid & 127;
    const int rgrp = tid >> 7;         // 0..3, 30 rows each
    float wa[F_DIM];
#pragma unroll
    for (int f = 0; f < F_DIM; f++) wa[f] = w1s[f * H_DIM + c];
    const float b1v = b1s[c];

    for (int tile = blockIdx.x; tile < n_tiles; tile += gridDim.x) {
        const int node0 = tile * ENC_TILE_NODES;

        // ---- load x (6 nodes x 160), clamped ----
        for (int i = tid; i < ENC_TILE_NODES * P_LANE * F_DIM; i += 512) {
            int j = i / (P_LANE * F_DIM);
            int nd = node0 + j; if (nd >= n_nodes) nd = n_nodes - 1;
            xs[i] = x_in[(size_t)nd * (P_LANE * F_DIM) + (i - j * (P_LANE * F_DIM))];
        }
        __syncthreads();
        if (tid < 2 * ENC_TILE_NODES)
            refv[tid] = xs[(tid >> 1) * 160 + 19 * 8 + (tid & 1)];
        __syncthreads();
        if (tid < 240) {
            int j = tid / 40, rem = tid % 40, t = rem >> 1, f = rem & 1;
            xs[j * 160 + t * 8 + f] -= refv[j * 2 + f];
        }
        __syncthreads();

        // ---- stage 1: A(r,c) = tf32(relu(b1 + x'[r].w1[:,c])), rows 0..119 ----
#pragma unroll 3
        for (int i = 0; i < 30; i++) {
            const int r = rgrp * 30 + i;
            const float4* xp = (const float4*)(xs + r * 8);
            const float4 x0 = xp[0], x1 = xp[1];
            float s = b1v;
            s = fmaf(x0.x, wa[0], s); s = fmaf(x0.y, wa[1], s);
            s = fmaf(x0.z, wa[2], s); s = fmaf(x0.w, wa[3], s);
            s = fmaf(x1.x, wa[4], s); s = fmaf(x1.y, wa[5], s);
            s = fmaf(x1.z, wa[6], s); s = fmaf(x1.w, wa[7], s);
            Au[r * SA + c] = f2tf32(fmaxf(s, 0.f));
        }
        __syncthreads();

        // ---- mma: D[128x128] = A @ B, warp tile 32x32, double-buffered ----
        float cfr[2][4][4];
#pragma unroll
        for (int mt = 0; mt < 2; mt++)
#pragma unroll
            for (int nt = 0; nt < 4; nt++)
#pragma unroll
                for (int q = 0; q < 4; q++) cfr[mt][nt][q] = 0.f;

        uint32_t abuf[2][2][4];
        uint32_t bbuf[2][8];

        auto load_frags = [&](int kc, int s) {
            const int k0 = kc * 8;
#pragma unroll
            for (int mt = 0; mt < 2; mt++) {
                const int rr = rm + mt * 16;
                abuf[s][mt][0] = Au[(rr + tg) * SA + k0 + tq];
                abuf[s][mt][1] = Au[(rr + tg + 8) * SA + k0 + tq];
                abuf[s][mt][2] = Au[(rr + tg) * SA + k0 + tq + 4];
                abuf[s][mt][3] = Au[(rr + tg + 8) * SA + k0 + tq + 4];
            }
            const uint32_t base = (uint32_t)((warp_n * 16 + kc) << 8);
            const uint4 q0 = *(const uint4*)(Bpu + base + (lane << 2));
            const uint4 q1 = *(const uint4*)(Bpu + base + 128 + (lane << 2));
            bbuf[s][0] = q0.x; bbuf[s][1] = q0.y; bbuf[s][2] = q0.z; bbuf[s][3] = q0.w;
            bbuf[s][4] = q1.x; bbuf[s][5] = q1.y; bbuf[s][6] = q1.z; bbuf[s][7] = q1.w;
        };

        load_frags(0, 0);
#pragma unroll
        for (int kc = 0; kc < 16; kc++) {
            const int cur = kc & 1, nxt = cur ^ 1;
            if (kc < 15) load_frags(kc + 1, nxt);
#pragma unroll
            for (int nt = 0; nt < 4; nt++) {
                mma_tf32(cfr[0][nt], abuf[cur][0], bbuf[cur][nt * 2], bbuf[cur][nt * 2 + 1]);
                mma_tf32(cfr[1][nt], abuf[cur][1], bbuf[cur][nt * 2], bbuf[cur][nt * 2 + 1]);
            }
        }
        __syncthreads();   // all A reads done; A memory becomes Dbuf

        // ---- store C frags to Dbuf (skip pad rows >= 120) ----
#pragma unroll
        for (int mt = 0; mt < 2; mt++) {
            const int rr = rm + mt * 16 + tg;
#pragma unroll
            for (int nt = 0; nt < 4; nt++) {
                const int cc = warp_n * 32 + nt * 8 + 2 * tq;
                if (rr < 120)
                    *(float2*)(A + rr * SA + cc) =
                        make_float2(cfr[mt][nt][0], cfr[mt][nt][1]);
                if (rr + 8 < 120)
                    *(float2*)(A + (rr + 8) * SA + cc) =
                        make_float2(cfr[mt][nt][2], cfr[mt][nt][3]);
            }
        }
        __syncthreads();

        // ---- per-node max over 20 rows + bias + relu -> g_ms ----
        for (int task = tid; task < ENC_TILE_NODES * H_DIM; task += 512) {
            const int j = task >> 7, cc = task & 127;
            const int nd = node0 + j;
            if (nd < n_nodes) {
                float m = -3.4e38f;
                const float* dp = A + (j * 20) * SA + cc;
#pragma unroll
                for (int r = 0; r < 20; r++) m = fmaxf(m, dp[r * SA]);
                ms_out[(size_t)nd * H_DIM + cc] = fmaxf(m + b2s[cc], 0.f);
            }
        }
        __syncthreads();
    }
}

// ---------------- tensor MLP: out = relu(in @ w + b), 128-row tiles ----------
#define MLP2_SMEM_FLOATS (16896 + 16384 + 128)
#define MLP2_SMEM_BYTES  (MLP2_SMEM_FLOATS * 4)

__global__ void __launch_bounds__(512, 1)
mlp_mma_kernel(const float* __restrict__ in_feat,
               const float* __restrict__ w, const float* __restrict__ b,
               float* __restrict__ out, int n_nodes)
{
    extern __shared__ float smem[];
    float* A     = smem;
    float* Bperm = A + 16896;
    float* bs    = Bperm + 16384;
    uint32_t* Au  = (uint32_t*)A;
    uint32_t* Bpu = (uint32_t*)Bperm;

    const int tid  = threadIdx.x;
    const int wid  = tid >> 5;
    const int lane = tid & 31;
    const int tg = lane >> 2;
    const int tq = lane & 3;
    const int warp_m = wid & 3;
    const int warp_n = wid >> 2;
    const int rm = warp_m * 32;

    load_Bperm(Bpu, w, tid, 512);
    if (tid < H_DIM) bs[tid] = b[tid];

    const int n0 = blockIdx.x * 128;
    {
        const int c  = tid & 127;
        const int r0 = (tid >> 7) * 32;
        for (int i = 0; i < 32; i++) {
            int r = r0 + i;
            int idx = n0 + r; if (idx >= n_nodes) idx = n_nodes - 1;
            Au[r * SA + c] = f2tf32(in_feat[(size_t)idx * H_DIM + c]);
        }
    }
    __syncthreads();

    float cfr[2][4][4];
#pragma unroll
    for (int mt = 0; mt < 2; mt++)
#pragma unroll
        for (int nt = 0; nt < 4; nt++)
#pragma unroll
            for (int q = 0; q < 4; q++) cfr[mt][nt][q] = 0.f;

    uint32_t abuf[2][2][4];
    uint32_t bbuf[2][8];

    auto load_frags = [&](int kc, int s) {
        const int k0 = kc * 8;
#pragma unroll
        for (int mt = 0; mt < 2; mt++) {
            const int rr = rm + mt * 16;
            abuf[s][mt][0] = Au[(rr + tg) * SA + k0 + tq];
            abuf[s][mt][1] = Au[(rr + tg + 8) * SA + k0 + tq];
            abuf[s][mt][2] = Au[(rr + tg) * SA + k0 + tq + 4];
            abuf[s][mt][3] = Au[(rr + tg + 8) * SA + k0 + tq + 4];
        }
        const uint32_t base = (uint32_t)((warp_n * 16 + kc) << 8);
        const uint4 q0 = *(const uint4*)(Bpu + base + (lane << 2));
        const uint4 q1 = *(const uint4*)(Bpu + base + 128 + (lane << 2));
        bbuf[s][0] = q0.x; bbuf[s][1] = q0.y; bbuf[s][2] = q0.z; bbuf[s][3] = q0.w;
        bbuf[s][4] = q1.x; bbuf[s][5] = q1.y; bbuf[s][6] = q1.z; bbuf[s][7] = q1.w;
    };

    load_frags(0, 0);
#pragma unroll
    for (int kc = 0; kc < 16; kc++) {
        const int cur = kc & 1, nxt = cur ^ 1;
        if (kc < 15) load_frags(kc + 1, nxt);
#pragma unroll
        for (int nt = 0; nt < 4; nt++) {
            mma_tf32(cfr[0][nt], abuf[cur][0], bbuf[cur][nt * 2], bbuf[cur][nt * 2 + 1]);
            mma_tf32(cfr[1][nt], abuf[cur][1], bbuf[cur][nt * 2], bbuf[cur][nt * 2 + 1]);
        }
    }

    // epilogue: bias + relu + direct STG
#pragma unroll
    for (int mt = 0; mt < 2; mt++) {
        const int rr = rm + mt * 16 + tg;
#pragma unroll
        for (int nt = 0; nt < 4; nt++) {
            const int cc = warp_n * 32 + nt * 8 + 2 * tq;
            const float2 bv = make_float2(bs[cc], bs[cc + 1]);
            const int nd0 = n0 + rr;
            if (nd0 < n_nodes)
                *(float2*)(out + (size_t)nd0 * H_DIM + cc) =
                    make_float2(fmaxf(cfr[mt][nt][0] + bv.x, 0.f),
                                fmaxf(cfr[mt][nt][1] + bv.y, 0.f));
            const int nd1 = nd0 + 8;
            if (nd1 < n_nodes)
                *(float2*)(out + (size_t)nd1 * H_DIM + cc) =
                    make_float2(fmaxf(cfr[mt][nt][2] + bv.x, 0.f),
                                fmaxf(cfr[mt][nt][3] + bv.y, 0.f));
        }
    }
}

// ---------------- edge scatter (segment_sum via vector RED) -----------------
__global__ void scatter_kernel(const int* __restrict__ src_idx,
                               const int* __restrict__ dst_idx, int n_edges,
                               const float* __restrict__ feat,
                               float* __restrict__ agg, float* __restrict__ deg)
{
    const int warp = (blockIdx.x * blockDim.x + threadIdx.x) >> 5;
    const int lane = threadIdx.x & 31;
    if (warp >= n_edges) return;
    const int s = src_idx[warp];
    const int d = dst_idx[warp];
    const float4 v = ((const float4*)(feat + (size_t)s * H_DIM))[lane];
    float4* a = ((float4*)(agg + (size_t)d * H_DIM)) + lane;
    asm volatile("red.global.add.v4.f32 [%0], {%1,%2,%3,%4};"
                 :: "l"(a), "f"(v.x), "f"(v.y), "f"(v.z), "f"(v.w) : "memory");
    if (lane == 0) atomicAdd(deg + d, 1.0f);
}

// ---------------- edge GNN node MLP: 8-node register-blocked GEMM -----------
#define GNN_NB 8
#define GNN_SMEM_FLOATS (2*H_DIM*H_DIM + H_DIM*H_DIM + 2*H_DIM + 2*H_DIM*GNN_NB + H_DIM*GNN_NB)
#define GNN_SMEM_BYTES  (GNN_SMEM_FLOATS * 4)

__global__ void __launch_bounds__(128, 1)
gnn_kernel(const float* __restrict__ node_in,
           const float* __restrict__ agg, const float* __restrict__ deg,
           const float* __restrict__ w1, const float* __restrict__ b1,
           const float* __restrict__ w2, const float* __restrict__ b2,
           float* __restrict__ out, int n_nodes, int nodes_per_block)
{
    extern __shared__ float smem[];
    float* w1s  = smem;
    float* w2s  = w1s + 2 * H_DIM * H_DIM;
    float* b1s  = w2s + H_DIM * H_DIM;
    float* b2s  = b1s + H_DIM;
    float* insT = b2s + H_DIM;
    float* hT   = insT + 2 * H_DIM * GNN_NB;

    const int tid = threadIdx.x;
    for (int i = tid; i < 2 * H_DIM * H_DIM; i += 128) w1s[i] = w1[i];
    for (int i = tid; i < H_DIM * H_DIM; i += 128) w2s[i] = w2[i];
    if (tid < H_DIM) { b1s[tid] = b1[tid]; b2s[tid] = b2[tid]; }
    __syncthreads();

    const float b1v = b1s[tid];
    const float b2v = b2s[tid];

    const int node0 = blockIdx.x * nodes_per_block;
    int node1 = node0 + nodes_per_block;
    if (node1 > n_nodes) node1 = n_nodes;

    const int jld = tid >> 4;
    const int lld = tid & 15;

    for (int g = node0; g < node1; g += GNN_NB) {
        {
            int nd = g + jld;
            if (nd >= n_nodes) nd = n_nodes - 1;
            const float invd = 1.0f / fmaxf(deg[nd], 1.0f);
            const float* np = node_in + (size_t)nd * H_DIM;
            const float* ap = agg + (size_t)nd * H_DIM;
#pragma unroll
            for (int r = 0; r < 8; r++) {
                const int k = lld + 16 * r;
                insT[k * GNN_NB + jld] = np[k];
                insT[(H_DIM + k) * GNN_NB + jld] = ap[k] * invd;
            }
        }
        __syncthreads();

        unsigned long long acc[4];
        {
            const unsigned long long bp = pack_dup(b1v);
#pragma unroll
            for (int j = 0; j < 4; j++) acc[j] = bp;
        }
#pragma unroll 4
        for (int k = 0; k < 2 * H_DIM; k++) {
            const unsigned long long wp = pack_dup(w1s[k * H_DIM + tid]);
            const ulonglong2* ip = ((const ulonglong2*)insT) + k * 2;
            const ulonglong2 a = ip[0];
            const ulonglong2 b = ip[1];
            ffma2(acc[0], a.x, wp);
            ffma2(acc[1], a.y, wp);
            ffma2(acc[2], b.x, wp);
            ffma2(acc[3], b.y, wp);
        }
        {
            const float2 v0 = unpack2(acc[0]);
            const float2 v1 = unpack2(acc[1]);
            const float2 v2 = unpack2(acc[2]);
            const float2 v3 = unpack2(acc[3]);
            float4* hp = (float4*)(hT + tid * GNN_NB);
            hp[0] = make_float4(fmaxf(v0.x, 0.f), fmaxf(v0.y, 0.f),
                                fmaxf(v1.x, 0.f), fmaxf(v1.y, 0.f));
            hp[1] = make_float4(fmaxf(v2.x, 0.f), fmaxf(v2.y, 0.f),
                                fmaxf(v3.x, 0.f), fmaxf(v3.y, 0.f));
        }
        __syncthreads();

        {
            const unsigned long long bp = pack_dup(b2v);
#pragma unroll
            for (int j = 0; j < 4; j++) acc[j] = bp;
        }
#pragma unroll 4
        for (int k = 0; k < H_DIM; k++) {
            const unsigned long long wp = pack_dup(w2s[k * H_DIM + tid]);
            const ulonglong2* hp = ((const ulonglong2*)hT) + k * 2;
            const ulonglong2 a = hp[0];
            const ulonglong2 b = hp[1];
            ffma2(acc[0], a.x, wp);
            ffma2(acc[1], a.y, wp);
            ffma2(acc[2], b.x, wp);
            ffma2(acc[3], b.y, wp);
        }

        float o[GNN_NB];
        {
            const float2 v0 = unpack2(acc[0]);
            const float2 v1 = unpack2(acc[1]);
            const float2 v2 = unpack2(acc[2]);
            const float2 v3 = unpack2(acc[3]);
            o[0] = fmaxf(v0.x, 0.f); o[1] = fmaxf(v0.y, 0.f);
            o[2] = fmaxf(v1.x, 0.f); o[3] = fmaxf(v1.y, 0.f);
            o[4] = fmaxf(v2.x, 0.f); o[5] = fmaxf(v2.y, 0.f);
            o[6] = fmaxf(v3.x, 0.f); o[7] = fmaxf(v3.y, 0.f);
        }
#pragma unroll
        for (int j = 0; j < GNN_NB; j++) {
            const int nd = g + j;
            if (nd < n_nodes) {
                const float nv = insT[tid * GNN_NB + j];
                out[(size_t)nd * H_DIM + tid] = nv + o[j];
            }
        }
        __syncthreads();
    }
}

// ---------------- launch -----------------------------------------------------
extern "C" void kernel_launch(void* const* d_in, const int* in_sizes, int n_in,
                              void* d_out, int out_size)
{
    const float* lane_points   = (const float*)d_in[0];
    const float* agent_history = (const float*)d_in[1];
    const int* e_ll = (const int*)d_in[2];
    const int* e_aa = (const int*)d_in[3];
    const int* e_la = (const int*)d_in[4];
    const float* lw1 = (const float*)d_in[5];
    const float* lb1 = (const float*)d_in[6];
    const float* lw2 = (const float*)d_in[7];
    const float* lb2 = (const float*)d_in[8];
    const float* lw3 = (const float*)d_in[9];
    const float* lb3 = (const float*)d_in[10];
    const float* aw1 = (const float*)d_in[11];
    const float* ab1 = (const float*)d_in[12];
    const float* aw2 = (const float*)d_in[13];
    const float* ab2 = (const float*)d_in[14];
    const float* aw3 = (const float*)d_in[15];
    const float* ab3 = (const float*)d_in[16];
    const float* ll_w1 = (const float*)d_in[17];
    const float* ll_b1 = (const float*)d_in[18];
    const float* ll_w2 = (const float*)d_in[19];
    const float* ll_b2 = (const float*)d_in[20];
    const float* aa_w1 = (const float*)d_in[21];
    const float* aa_b1 = (const float*)d_in[22];
    const float* aa_w2 = (const float*)d_in[23];
    const float* aa_b2 = (const float*)d_in[24];
    const float* la_w1 = (const float*)d_in[25];
    const float* la_b1 = (const float*)d_in[26];
    const float* la_w2 = (const float*)d_in[27];
    const float* la_b2 = (const float*)d_in[28];

    float* out = (float*)d_out;
    float* lane_out  = out;
    float* agent_out = out + (size_t)N_LANE * H_DIM;

    float *p_lane_enc, *p_agent_enc, *p_lane_agg, *p_agent_agg, *p_ms, *p_deg_l, *p_deg_a;
    cudaGetSymbolAddress((void**)&p_lane_enc,  g_lane_enc);
    cudaGetSymbolAddress((void**)&p_agent_enc, g_agent_enc);
    cudaGetSymbolAddress((void**)&p_lane_agg,  g_lane_agg);
    cudaGetSymbolAddress((void**)&p_agent_agg, g_agent_agg);
    cudaGetSymbolAddress((void**)&p_ms,        g_ms);
    cudaGetSymbolAddress((void**)&p_deg_l,     g_deg_l);
    cudaGetSymbolAddress((void**)&p_deg_a,     g_deg_a);

    cudaFuncSetAttribute(enc_mma_kernel, cudaFuncAttributeMaxDynamicSharedMemorySize, ENC3_SMEM_BYTES);
    cudaFuncSetAttribute(mlp_mma_kernel, cudaFuncAttributeMaxDynamicSharedMemorySize, MLP2_SMEM_BYTES);
    cudaFuncSetAttribute(gnn_kernel,     cudaFuncAttributeMaxDynamicSharedMemorySize, GNN_SMEM_BYTES);

    const int agent_tiles = (N_AGENT + ENC_TILE_NODES - 1) / ENC_TILE_NODES;
    const int lane_tiles  = (N_LANE + ENC_TILE_NODES - 1) / ENC_TILE_NODES;

    zero_all_kernel<<<2048, 256>>>();
    enc_mma_kernel<<<148, 512, ENC3_SMEM_BYTES>>>(
        agent_history, aw1, ab1, aw2, ab2, p_ms, N_AGENT, agent_tiles);
    mlp_mma_kernel<<<(N_AGENT + 127) / 128, 512, MLP2_SMEM_BYTES>>>(
        p_ms, aw3, ab3, p_agent_enc, N_AGENT);
    enc_mma_kernel<<<148, 512, ENC3_SMEM_BYTES>>>(
        lane_points, lw1, lb1, lw2, lb2, p_ms, N_LANE, lane_tiles);
    mlp_mma_kernel<<<(N_LANE + 127) / 128, 512, MLP2_SMEM_BYTES>>>(
        p_ms, lw3, lb3, p_lane_enc, N_LANE);

    scatter_kernel<<<(E_LL + 7) / 8, 256>>>(e_ll, e_ll + E_LL, E_LL,
                                            p_lane_enc, p_lane_agg, p_deg_l);
    gnn_kernel<<<(N_LANE + 71) / 72, 128, GNN_SMEM_BYTES>>>(
        p_lane_enc, p_lane_agg, p_deg_l, ll_w1, ll_b1, ll_w2, ll_b2,
        lane_out, N_LANE, 72);

    scatter_kernel<<<(E_AA + 7) / 8, 256>>>(e_aa, e_aa + E_AA, E_AA,
                                            p_agent_enc, p_agent_agg, p_deg_a);
    gnn_kernel<<<(N_AGENT + 31) / 32, 128, GNN_SMEM_BYTES>>>(
        p_agent_enc, p_agent_agg, p_deg_a, aa_w1, aa_b1, aa_w2, aa_b2,
        agent_out, N_AGENT, 32);

    zero_agent_kernel<<<1024, 256>>>();
    scatter_kernel<<<(E_LA + 7) / 8, 256>>>(e_la, e_la + E_LA, E_LA,
                                            lane_out, p_agent_agg, p_deg_a);
    gnn_kernel<<<(N_AGENT + 31) / 32, 128, GNN_SMEM_BYTES>>>(
        agent_out, p_agent_agg, p_deg_a, la_w1, la_b1, la_w2, la_b2,
        agent_out, N_AGENT, 32);
}

// round 9
// speedup vs baseline: 1.7812x; 1.3125x over previous
#include <cuda_runtime.h>
#include <cstddef>
#include <cstdint>

#define N_LANE  20000
#define P_LANE  20
#define N_AGENT 4000
#define T_AGENT 20
#define F_DIM   8
#define H_DIM   128
#define E_LL    640000
#define E_AA    128000
#define E_LA    200000

// ---------------- scratch (device globals; no allocation allowed) -----------
__device__ float g_lane_enc [N_LANE  * H_DIM];
__device__ float g_agent_enc[N_AGENT * H_DIM];
__device__ float g_lane_agg [N_LANE  * H_DIM];
__device__ float g_agent_agg[N_AGENT * H_DIM];
__device__ float g_ms      [N_LANE  * H_DIM];
__device__ float g_deg_l[N_LANE];
__device__ float g_deg_a[N_AGENT];

// ---------------- PTX helpers -------------------------------------------------
__device__ __forceinline__ uint32_t smem_u32(const void* p) {
    uint32_t a;
    asm("{ .reg .u64 t; cvta.to.shared.u64 t, %1; cvt.u32.u64 %0, t; }" : "=r"(a) : "l"(p));
    return a;
}
__device__ __forceinline__ void cp_async16(float* dst, const float* src) {
    asm volatile("cp.async.cg.shared.global [%0], [%1], 16;"
                 :: "r"(smem_u32(dst)), "l"(src));
}
#define CP_COMMIT() asm volatile("cp.async.commit_group;" ::: "memory")
#define CP_WAIT0()  asm volatile("cp.async.wait_group 0;" ::: "memory")

__device__ __forceinline__ uint32_t f2tf32(float f) {
    uint32_t u;
    asm("cvt.rna.tf32.f32 %0, %1;" : "=r"(u) : "f"(f));
    return u;
}
__device__ __forceinline__ void mma_tf32(float c[4], const uint32_t a[4],
                                         uint32_t b0, uint32_t b1) {
    asm("mma.sync.aligned.m16n8k8.row.col.f32.tf32.tf32.f32 "
        "{%0,%1,%2,%3}, {%4,%5,%6,%7}, {%8,%9}, {%0,%1,%2,%3};"
        : "+f"(c[0]), "+f"(c[1]), "+f"(c[2]), "+f"(c[3])
        : "r"(a[0]), "r"(a[1]), "r"(a[2]), "r"(a[3]), "r"(b0), "r"(b1));
}

#define SA 132

// ---------------- shared Bperm init (quad-major, 32-col n-groups) ------------
// Chunk (ng*16+kc) = 256 u32: [q 0..1][lane 0..31][e 0..3]; re = q*4+e,
// nt = re>>1, p = re&1 -> element (k = kc*8 + (l&3) + 4p, n = ng*32 + nt*8 + (l>>2))
__device__ __forceinline__ void load_Bperm(uint32_t* Bpu, const float* __restrict__ w,
                                           int tid, int nthreads) {
    for (int idx = tid; idx < 16384; idx += nthreads) {
        const int chunk = idx >> 8;            // 0..63
        const int q = (idx >> 7) & 1;
        const int l = (idx >> 2) & 31;
        const int e = idx & 3;
        const int kc = chunk & 15, ng = chunk >> 4;
        const int re = q * 4 + e;
        const int nt = re >> 1, p = re & 1;
        const int k = kc * 8 + (l & 3) + 4 * p;
        const int n = ng * 32 + nt * 8 + (l >> 2);
        Bpu[idx] = f2tf32(w[k * H_DIM + n]);
    }
}

// ---------------- shared 16-kc double-buffered mma pass ----------------------
__device__ __forceinline__ void mma_tile_16kc(float cfr[2][4][4],
                                              const uint32_t* __restrict__ Au,
                                              const uint32_t* __restrict__ Bpu,
                                              int rm, int warp_n, int lane,
                                              int tg, int tq) {
    uint32_t abuf[2][2][4];
    uint32_t bbuf[2][8];

    auto load_frags = [&](int kc, int s) {
        const int k0 = kc * 8;
#pragma unroll
        for (int mt = 0; mt < 2; mt++) {
            const int rr = rm + mt * 16;
            abuf[s][mt][0] = Au[(rr + tg) * SA + k0 + tq];
            abuf[s][mt][1] = Au[(rr + tg + 8) * SA + k0 + tq];
            abuf[s][mt][2] = Au[(rr + tg) * SA + k0 + tq + 4];
            abuf[s][mt][3] = Au[(rr + tg + 8) * SA + k0 + tq + 4];
        }
        const uint32_t base = (uint32_t)((warp_n * 16 + kc) << 8);
        const uint4 q0 = *(const uint4*)(Bpu + base + (lane << 2));
        const uint4 q1 = *(const uint4*)(Bpu + base + 128 + (lane << 2));
        bbuf[s][0] = q0.x; bbuf[s][1] = q0.y; bbuf[s][2] = q0.z; bbuf[s][3] = q0.w;
        bbuf[s][4] = q1.x; bbuf[s][5] = q1.y; bbuf[s][6] = q1.z; bbuf[s][7] = q1.w;
    };

    load_frags(0, 0);
#pragma unroll
    for (int kc = 0; kc < 16; kc++) {
        const int cur = kc & 1, nxt = cur ^ 1;
        if (kc < 15) load_frags(kc + 1, nxt);
#pragma unroll
        for (int nt = 0; nt < 4; nt++) {
            mma_tf32(cfr[0][nt], abuf[cur][0], bbuf[cur][nt * 2], bbuf[cur][nt * 2 + 1]);
            mma_tf32(cfr[1][nt], abuf[cur][1], bbuf[cur][nt * 2], bbuf[cur][nt * 2 + 1]);
        }
    }
}

// ---------------- zero kernels ----------------------------------------------
__global__ void zero_all_kernel() {
    int i = blockIdx.x * blockDim.x + threadIdx.x;
    int stride = gridDim.x * blockDim.x;
    for (int k = i; k < N_LANE * H_DIM; k += stride) g_lane_agg[k] = 0.f;
    for (int k = i; k < N_AGENT * H_DIM; k += stride) g_agent_agg[k] = 0.f;
    for (int k = i; k < N_LANE; k += stride) g_deg_l[k] = 0.f;
    for (int k = i; k < N_AGENT; k += stride) g_deg_a[k] = 0.f;
}
__global__ void zero_agent_kernel() {
    int i = blockIdx.x * blockDim.x + threadIdx.x;
    int stride = gridDim.x * blockDim.x;
    for (int k = i; k < N_AGENT * H_DIM; k += stride) g_agent_agg[k] = 0.f;
    for (int k = i; k < N_AGENT; k += stride) g_deg_a[k] = 0.f;
}

// ---------------- tensor encoder (stages 1+2+max), 512 threads ---------------
// smem floats: A 16896 | Bperm 16384 | xs 2x960 | w1s 1024 | b1s 128 | b2s 128
#define ENC_TILE_NODES 6
#define ENC4_SMEM_FLOATS (16896 + 16384 + 1920 + 1024 + 128 + 128)
#define ENC4_SMEM_BYTES  (ENC4_SMEM_FLOATS * 4)

__global__ void __launch_bounds__(512, 1)
enc_mma_kernel(const float* __restrict__ x_in,
               const float* __restrict__ w1, const float* __restrict__ b1,
               const float* __restrict__ w2, const float* __restrict__ b2,
               float* __restrict__ ms_out, int n_nodes, int n_tiles)
{
    extern __shared__ float smem[];
    float* A     = smem;               // tf32 bits during mma; f32 Dbuf after
    float* Bperm = A + 16896;          // 16384
    float* xs    = Bperm + 16384;      // 2 x 960
    float* w1s   = xs + 1920;
    float* b1s   = w1s + 1024;
    float* b2s   = b1s + 128;

    uint32_t* Au  = (uint32_t*)A;
    uint32_t* Bpu = (uint32_t*)Bperm;

    const int tid  = threadIdx.x;      // 0..511
    const int wid  = tid >> 5;         // 0..15
    const int lane = tid & 31;
    const int tg = lane >> 2;
    const int tq = lane & 3;
    const int warp_m = wid & 3;        // 4 x 32-row groups
    const int warp_n = wid >> 2;       // 4 x 32-col groups
    const int rm = warp_m * 32;

    load_Bperm(Bpu, w2, tid, 512);
    for (int i = tid; i < F_DIM * H_DIM; i += 512) w1s[i] = w1[i];
    if (tid < H_DIM) { b1s[tid] = b1[tid]; b2s[tid] = b2[tid]; }
    // zero pad rows 120..127 ONCE (C-stores below never touch them)
    for (int i = tid; i < 8 * SA; i += 512)
        Au[120 * SA + i] = 0;
    __syncthreads();                   // REQUIRED before reading w1s/b1s below

    const int c    = tid & 127;
    const int rgrp = tid >> 7;         // 0..3, 30 rows each
    float wa[F_DIM];
#pragma unroll
    for (int f = 0; f < F_DIM; f++) wa[f] = w1s[f * H_DIM + c];
    const float b1v = b1s[c];

    // prefetch: 240 x 16B chunks per tile (6 nodes x 160 floats)
    auto prefetch = [&](int tile, int buf) {
        const int node0 = tile * ENC_TILE_NODES;
        for (int i = tid; i < 240; i += 512) {
            int j = i / 40;
            int nd = node0 + j; if (nd >= n_nodes) nd = n_nodes - 1;
            cp_async16(xs + buf * 960 + i * 4,
                       x_in + (size_t)nd * 160 + (i - j * 40) * 4);
        }
    };

    int buf = 0;
    if (blockIdx.x < n_tiles) { prefetch(blockIdx.x, 0); }
    CP_COMMIT();

    for (int tile = blockIdx.x; tile < n_tiles; tile += gridDim.x) {
        const int node0 = tile * ENC_TILE_NODES;

        CP_WAIT0();
        __syncthreads();
        const float* xc = xs + buf * 960;

        // prefetch next tile into other buffer
        {
            int ntile = tile + gridDim.x;
            if (ntile < n_tiles) prefetch(ntile, buf ^ 1);
            CP_COMMIT();
        }

        // ---- stage 1: A(r,c) = tf32(relu(b1 + x'[r].w1[:,c])), rows 0..119 ----
#pragma unroll 3
        for (int i = 0; i < 30; i++) {
            const int r = rgrp * 30 + i;
            const int j = r / 20;
            const float rx = xc[j * 160 + 152];
            const float ry = xc[j * 160 + 153];
            const float4* xp = (const float4*)(xc + r * 8);
            const float4 x0 = xp[0], x1 = xp[1];
            float s = b1v;
            s = fmaf(x0.x - rx, wa[0], s); s = fmaf(x0.y - ry, wa[1], s);
            s = fmaf(x0.z, wa[2], s); s = fmaf(x0.w, wa[3], s);
            s = fmaf(x1.x, wa[4], s); s = fmaf(x1.y, wa[5], s);
            s = fmaf(x1.z, wa[6], s); s = fmaf(x1.w, wa[7], s);
            Au[r * SA + c] = f2tf32(fmaxf(s, 0.f));
        }
        __syncthreads();

        // ---- mma: D[128x128] = A @ B, warp tile 32x32 ----
        float cfr[2][4][4];
#pragma unroll
        for (int mt = 0; mt < 2; mt++)
#pragma unroll
            for (int nt = 0; nt < 4; nt++)
#pragma unroll
                for (int q = 0; q < 4; q++) cfr[mt][nt][q] = 0.f;

        mma_tile_16kc(cfr, Au, Bpu, rm, warp_n, lane, tg, tq);
        __syncthreads();   // all A reads done; A memory becomes Dbuf

        // ---- store C frags to Dbuf (skip pad rows >= 120) ----
#pragma unroll
        for (int mt = 0; mt < 2; mt++) {
            const int rr = rm + mt * 16 + tg;
#pragma unroll
            for (int nt = 0; nt < 4; nt++) {
                const int cc = warp_n * 32 + nt * 8 + 2 * tq;
                if (rr < 120)
                    *(float2*)(A + rr * SA + cc) =
                        make_float2(cfr[mt][nt][0], cfr[mt][nt][1]);
                if (rr + 8 < 120)
                    *(float2*)(A + (rr + 8) * SA + cc) =
                        make_float2(cfr[mt][nt][2], cfr[mt][nt][3]);
            }
        }
        __syncthreads();

        // ---- per-node max over 20 rows + bias + relu -> g_ms ----
        for (int task = tid; task < ENC_TILE_NODES * H_DIM; task += 512) {
            const int j = task >> 7, cc = task & 127;
            const int nd = node0 + j;
            if (nd < n_nodes) {
                float m = -3.4e38f;
                const float* dp = A + (j * 20) * SA + cc;
#pragma unroll
                for (int r = 0; r < 20; r++) m = fmaxf(m, dp[r * SA]);
                ms_out[(size_t)nd * H_DIM + cc] = fmaxf(m + b2s[cc], 0.f);
            }
        }
        __syncthreads();
        buf ^= 1;
    }
}

// ---------------- tensor MLP: out = relu(in @ w + b), 128-row tiles ----------
#define MLP2_SMEM_FLOATS (16896 + 16384 + 128)
#define MLP2_SMEM_BYTES  (MLP2_SMEM_FLOATS * 4)

__global__ void __launch_bounds__(512, 1)
mlp_mma_kernel(const float* __restrict__ in_feat,
               const float* __restrict__ w, const float* __restrict__ b,
               float* __restrict__ out, int n_nodes)
{
    extern __shared__ float smem[];
    float* A     = smem;
    float* Bperm = A + 16896;
    float* bs    = Bperm + 16384;
    uint32_t* Au  = (uint32_t*)A;
    uint32_t* Bpu = (uint32_t*)Bperm;

    const int tid  = threadIdx.x;
    const int wid  = tid >> 5;
    const int lane = tid & 31;
    const int tg = lane >> 2;
    const int tq = lane & 3;
    const int warp_m = wid & 3;
    const int warp_n = wid >> 2;
    const int rm = warp_m * 32;

    load_Bperm(Bpu, w, tid, 512);
    if (tid < H_DIM) bs[tid] = b[tid];

    const int n0 = blockIdx.x * 128;
    {
        const int c  = tid & 127;
        const int r0 = (tid >> 7) * 32;
        for (int i = 0; i < 32; i++) {
            int r = r0 + i;
            int idx = n0 + r; if (idx >= n_nodes) idx = n_nodes - 1;
            Au[r * SA + c] = f2tf32(in_feat[(size_t)idx * H_DIM + c]);
        }
    }
    __syncthreads();

    float cfr[2][4][4];
#pragma unroll
    for (int mt = 0; mt < 2; mt++)
#pragma unroll
        for (int nt = 0; nt < 4; nt++)
#pragma unroll
            for (int q = 0; q < 4; q++) cfr[mt][nt][q] = 0.f;

    mma_tile_16kc(cfr, Au, Bpu, rm, warp_n, lane, tg, tq);

    // epilogue: bias + relu + direct STG
#pragma unroll
    for (int mt = 0; mt < 2; mt++) {
        const int rr = rm + mt * 16 + tg;
#pragma unroll
        for (int nt = 0; nt < 4; nt++) {
            const int cc = warp_n * 32 + nt * 8 + 2 * tq;
            const float2 bv = make_float2(bs[cc], bs[cc + 1]);
            const int nd0 = n0 + rr;
            if (nd0 < n_nodes)
                *(float2*)(out + (size_t)nd0 * H_DIM + cc) =
                    make_float2(fmaxf(cfr[mt][nt][0] + bv.x, 0.f),
                                fmaxf(cfr[mt][nt][1] + bv.y, 0.f));
            const int nd1 = nd0 + 8;
            if (nd1 < n_nodes)
                *(float2*)(out + (size_t)nd1 * H_DIM + cc) =
                    make_float2(fmaxf(cfr[mt][nt][2] + bv.x, 0.f),
                                fmaxf(cfr[mt][nt][3] + bv.y, 0.f));
        }
    }
}

// ---------------- tensor GNN: out = node + relu(relu([node|agg]@w1+b1)@w2+b2)
// smem: A 16896 | Bperm 16384 | bs1 128 | bs2 128
#define GNN2_SMEM_FLOATS (16896 + 16384 + 128 + 128)
#define GNN2_SMEM_BYTES  (GNN2_SMEM_FLOATS * 4)

__global__ void __launch_bounds__(512, 1)
gnn_mma_kernel(const float* __restrict__ node_in,
               const float* __restrict__ agg, const float* __restrict__ deg,
               const float* __restrict__ w1, const float* __restrict__ b1,
               const float* __restrict__ w2, const float* __restrict__ b2,
               float* __restrict__ out, int n_nodes)
{
    extern __shared__ float smem[];
    float* A     = smem;
    float* Bperm = A + 16896;
    float* bs1   = Bperm + 16384;
    float* bs2   = bs1 + 128;
    uint32_t* Au  = (uint32_t*)A;
    uint32_t* Bpu = (uint32_t*)Bperm;

    const int tid  = threadIdx.x;
    const int wid  = tid >> 5;
    const int lane = tid & 31;
    const int tg = lane >> 2;
    const int tq = lane & 3;
    const int warp_m = wid & 3;
    const int warp_n = wid >> 2;
    const int rm = warp_m * 32;
    const int n0 = blockIdx.x * 128;

    const int c  = tid & 127;
    const int r0 = (tid >> 7) * 32;

    // ---- phase 0: Bp = w1[k=0..127], A = node rows ----
    load_Bperm(Bpu, w1, tid, 512);
    if (tid < H_DIM) { bs1[tid] = b1[tid]; bs2[tid] = b2[tid]; }
    for (int i = 0; i < 32; i++) {
        int r = r0 + i;
        int idx = n0 + r; if (idx >= n_nodes) idx = n_nodes - 1;
        Au[r * SA + c] = f2tf32(node_in[(size_t)idx * H_DIM + c]);
    }
    __syncthreads();

    float cfr[2][4][4];
#pragma unroll
    for (int mt = 0; mt < 2; mt++)
#pragma unroll
        for (int nt = 0; nt < 4; nt++)
#pragma unroll
            for (int q = 0; q < 4; q++) cfr[mt][nt][q] = 0.f;

    mma_tile_16kc(cfr, Au, Bpu, rm, warp_n, lane, tg, tq);
    __syncthreads();

    // ---- phase 2: Bp = w1[k=128..255], A = agg/deg ----
    load_Bperm(Bpu, w1 + 128 * H_DIM, tid, 512);
    for (int i = 0; i < 32; i++) {
        int r = r0 + i;
        int idx = n0 + r; if (idx >= n_nodes) idx = n_nodes - 1;
        const float invd = 1.0f / fmaxf(deg[idx], 1.0f);
        Au[r * SA + c] = f2tf32(agg[(size_t)idx * H_DIM + c] * invd);
    }
    __syncthreads();

    mma_tile_16kc(cfr, Au, Bpu, rm, warp_n, lane, tg, tq);
    __syncthreads();

    // ---- phase 4: h = relu(cfr + b1) -> A (tf32);  Bp = w2 ----
#pragma unroll
    for (int mt = 0; mt < 2; mt++) {
        const int rr = rm + mt * 16 + tg;
#pragma unroll
        for (int nt = 0; nt < 4; nt++) {
            const int cc = warp_n * 32 + nt * 8 + 2 * tq;
            Au[rr * SA + cc]     = f2tf32(fmaxf(cfr[mt][nt][0] + bs1[cc], 0.f));
            Au[rr * SA + cc + 1] = f2tf32(fmaxf(cfr[mt][nt][1] + bs1[cc + 1], 0.f));
            Au[(rr + 8) * SA + cc]     = f2tf32(fmaxf(cfr[mt][nt][2] + bs1[cc], 0.f));
            Au[(rr + 8) * SA + cc + 1] = f2tf32(fmaxf(cfr[mt][nt][3] + bs1[cc + 1], 0.f));
        }
    }
    load_Bperm(Bpu, w2, tid, 512);
    __syncthreads();

    // ---- phase 6: layer 2 mma ----
#pragma unroll
    for (int mt = 0; mt < 2; mt++)
#pragma unroll
        for (int nt = 0; nt < 4; nt++)
#pragma unroll
            for (int q = 0; q < 4; q++) cfr[mt][nt][q] = 0.f;

    mma_tile_16kc(cfr, Au, Bpu, rm, warp_n, lane, tg, tq);

    // ---- epilogue: out = node + relu(cfr + b2) ----
#pragma unroll
    for (int mt = 0; mt < 2; mt++) {
        const int rr = rm + mt * 16 + tg;
#pragma unroll
        for (int nt = 0; nt < 4; nt++) {
            const int cc = warp_n * 32 + nt * 8 + 2 * tq;
            const float2 bv = make_float2(bs2[cc], bs2[cc + 1]);
            const int nd0 = n0 + rr;
            if (nd0 < n_nodes) {
                const float2 nv = *(const float2*)(node_in + (size_t)nd0 * H_DIM + cc);
                *(float2*)(out + (size_t)nd0 * H_DIM + cc) =
                    make_float2(nv.x + fmaxf(cfr[mt][nt][0] + bv.x, 0.f),
                                nv.y + fmaxf(cfr[mt][nt][1] + bv.y, 0.f));
            }
            const int nd1 = nd0 + 8;
            if (nd1 < n_nodes) {
                const float2 nv = *(const float2*)(node_in + (size_t)nd1 * H_DIM + cc);
                *(float2*)(out + (size_t)nd1 * H_DIM + cc) =
                    make_float2(nv.x + fmaxf(cfr[mt][nt][2] + bv.x, 0.f),
                                nv.y + fmaxf(cfr[mt][nt][3] + bv.y, 0.f));
            }
        }
    }
}

// ---------------- edge scatter (segment_sum via vector RED) -----------------
__global__ void scatter_kernel(const int* __restrict__ src_idx,
                               const int* __restrict__ dst_idx, int n_edges,
                               const float* __restrict__ feat,
                               float* __restrict__ agg, float* __restrict__ deg)
{
    const int warp = (blockIdx.x * blockDim.x + threadIdx.x) >> 5;
    const int lane = threadIdx.x & 31;
    if (warp >= n_edges) return;
    const int s = src_idx[warp];
    const int d = dst_idx[warp];
    const float4 v = ((const float4*)(feat + (size_t)s * H_DIM))[lane];
    float4* a = ((float4*)(agg + (size_t)d * H_DIM)) + lane;
    asm volatile("red.global.add.v4.f32 [%0], {%1,%2,%3,%4};"
                 :: "l"(a), "f"(v.x), "f"(v.y), "f"(v.z), "f"(v.w) : "memory");
    if (lane == 0) atomicAdd(deg + d, 1.0f);
}

// ---------------- launch -----------------------------------------------------
extern "C" void kernel_launch(void* const* d_in, const int* in_sizes, int n_in,
                              void* d_out, int out_size)
{
    const float* lane_points   = (const float*)d_in[0];
    const float* agent_history = (const float*)d_in[1];
    const int* e_ll = (const int*)d_in[2];
    const int* e_aa = (const int*)d_in[3];
    const int* e_la = (const int*)d_in[4];
    const float* lw1 = (const float*)d_in[5];
    const float* lb1 = (const float*)d_in[6];
    const float* lw2 = (const float*)d_in[7];
    const float* lb2 = (const float*)d_in[8];
    const float* lw3 = (const float*)d_in[9];
    const float* lb3 = (const float*)d_in[10];
    const float* aw1 = (const float*)d_in[11];
    const float* ab1 = (const float*)d_in[12];
    const float* aw2 = (const float*)d_in[13];
    const float* ab2 = (const float*)d_in[14];
    const float* aw3 = (const float*)d_in[15];
    const float* ab3 = (const float*)d_in[16];
    const float* ll_w1 = (const float*)d_in[17];
    const float* ll_b1 = (const float*)d_in[18];
    const float* ll_w2 = (const float*)d_in[19];
    const float* ll_b2 = (const float*)d_in[20];
    const float* aa_w1 = (const float*)d_in[21];
    const float* aa_b1 = (const float*)d_in[22];
    const float* aa_w2 = (const float*)d_in[23];
    const float* aa_b2 = (const float*)d_in[24];
    const float* la_w1 = (const float*)d_in[25];
    const float* la_b1 = (const float*)d_in[26];
    const float* la_w2 = (const float*)d_in[27];
    const float* la_b2 = (const float*)d_in[28];

    float* out = (float*)d_out;
    float* lane_out  = out;
    float* agent_out = out + (size_t)N_LANE * H_DIM;

    float *p_lane_enc, *p_agent_enc, *p_lane_agg, *p_agent_agg, *p_ms, *p_deg_l, *p_deg_a;
    cudaGetSymbolAddress((void**)&p_lane_enc,  g_lane_enc);
    cudaGetSymbolAddress((void**)&p_agent_enc, g_agent_enc);
    cudaGetSymbolAddress((void**)&p_lane_agg,  g_lane_agg);
    cudaGetSymbolAddress((void**)&p_agent_agg, g_agent_agg);
    cudaGetSymbolAddress((void**)&p_ms,        g_ms);
    cudaGetSymbolAddress((void**)&p_deg_l,     g_deg_l);
    cudaGetSymbolAddress((void**)&p_deg_a,     g_deg_a);

    cudaFuncSetAttribute(enc_mma_kernel, cudaFuncAttributeMaxDynamicSharedMemorySize, ENC4_SMEM_BYTES);
    cudaFuncSetAttribute(mlp_mma_kernel, cudaFuncAttributeMaxDynamicSharedMemorySize, MLP2_SMEM_BYTES);
    cudaFuncSetAttribute(gnn_mma_kernel, cudaFuncAttributeMaxDynamicSharedMemorySize, GNN2_SMEM_BYTES);

    const int agent_tiles = (N_AGENT + ENC_TILE_NODES - 1) / ENC_TILE_NODES;
    const int lane_tiles  = (N_LANE + ENC_TILE_NODES - 1) / ENC_TILE_NODES;
    const int lane_blks   = (N_LANE + 127) / 128;
    const int agent_blks  = (N_AGENT + 127) / 128;

    zero_all_kernel<<<2048, 256>>>();
    enc_mma_kernel<<<148, 512, ENC4_SMEM_BYTES>>>(
        agent_history, aw1, ab1, aw2, ab2, p_ms, N_AGENT, agent_tiles);
    mlp_mma_kernel<<<agent_blks, 512, MLP2_SMEM_BYTES>>>(
        p_ms, aw3, ab3, p_agent_enc, N_AGENT);
    enc_mma_kernel<<<148, 512, ENC4_SMEM_BYTES>>>(
        lane_points, lw1, lb1, lw2, lb2, p_ms, N_LANE, lane_tiles);
    mlp_mma_kernel<<<lane_blks, 512, MLP2_SMEM_BYTES>>>(
        p_ms, lw3, lb3, p_lane_enc, N_LANE);

    scatter_kernel<<<(E_LL + 7) / 8, 256>>>(e_ll, e_ll + E_LL, E_LL,
                                            p_lane_enc, p_lane_agg, p_deg_l);
    gnn_mma_kernel<<<lane_blks, 512, GNN2_SMEM_BYTES>>>(
        p_lane_enc, p_lane_agg, p_deg_l, ll_w1, ll_b1, ll_w2, ll_b2,
        lane_out, N_LANE);

    scatter_kernel<<<(E_AA + 7) / 8, 256>>>(e_aa, e_aa + E_AA, E_AA,
                                            p_agent_enc, p_agent_agg, p_deg_a);
    gnn_mma_kernel<<<agent_blks, 512, GNN2_SMEM_BYTES>>>(
        p_agent_enc, p_agent_agg, p_deg_a, aa_w1, aa_b1, aa_w2, aa_b2,
        agent_out, N_AGENT);

    zero_agent_kernel<<<1024, 256>>>();
    scatter_kernel<<<(E_LA + 7) / 8, 256>>>(e_la, e_la + E_LA, E_LA,
                                            lane_out, p_agent_agg, p_deg_a);
    gnn_mma_kernel<<<agent_blks, 512, GNN2_SMEM_BYTES>>>(
        agent_out, p_agent_agg, p_deg_a, la_w1, la_b1, la_w2, la_b2,
        agent_out, N_AGENT);
}

// round 11
// speedup vs baseline: 1.9309x; 1.0840x over previous
#include <cuda_runtime.h>
#include <cstddef>
#include <cstdint>

#define N_LANE  20000
#define P_LANE  20
#define N_AGENT 4000
#define T_AGENT 20
#define F_DIM   8
#define H_DIM   128
#define E_LL    640000
#define E_AA    128000
#define E_LA    200000

#define AGENT_CTAS 25
#define TOTAL_CTAS 148
#define LANE_BLKS  157      // ceil(20000/128)
#define AGENT_BLKS 32       // ceil(4000/128)

// ---------------- scratch (device globals; no allocation allowed) -----------
__device__ float g_lane_enc [N_LANE  * H_DIM];
__device__ float g_agent_enc[N_AGENT * H_DIM];
__device__ float g_lane_agg [N_LANE  * H_DIM];
__device__ float g_agent_agg[N_AGENT * H_DIM];
__device__ float g_ms_l    [N_LANE  * H_DIM];
__device__ float g_ms_a    [N_AGENT * H_DIM];
__device__ float g_deg_l[N_LANE];
__device__ float g_deg_a[N_AGENT];

// ---------------- PTX helpers -------------------------------------------------
__device__ __forceinline__ uint32_t smem_u32(const void* p) {
    uint32_t a;
    asm("{ .reg .u64 t; cvta.to.shared.u64 t, %1; cvt.u32.u64 %0, t; }" : "=r"(a) : "l"(p));
    return a;
}
__device__ __forceinline__ void cp_async16(float* dst, const float* src) {
    asm volatile("cp.async.cg.shared.global [%0], [%1], 16;"
                 :: "r"(smem_u32(dst)), "l"(src));
}
#define CP_COMMIT() asm volatile("cp.async.commit_group;" ::: "memory")
#define CP_WAIT0()  asm volatile("cp.async.wait_group 0;" ::: "memory")

__device__ __forceinline__ uint32_t f2tf32(float f) {
    uint32_t u;
    asm("cvt.rna.tf32.f32 %0, %1;" : "=r"(u) : "f"(f));
    return u;
}
__device__ __forceinline__ void mma_tf32(float c[4], const uint32_t a[4],
                                         uint32_t b0, uint32_t b1) {
    asm("mma.sync.aligned.m16n8k8.row.col.f32.tf32.tf32.f32 "
        "{%0,%1,%2,%3}, {%4,%5,%6,%7}, {%8,%9}, {%0,%1,%2,%3};"
        : "+f"(c[0]), "+f"(c[1]), "+f"(c[2]), "+f"(c[3])
        : "r"(a[0]), "r"(a[1]), "r"(a[2]), "r"(a[3]), "r"(b0), "r"(b1));
}

#define SA 132

// ---------------- shared Bperm init (quad-major, 32-col n-groups) ------------
__device__ __forceinline__ void load_Bperm(uint32_t* Bpu, const float* __restrict__ w,
                                           int tid, int nthreads) {
    for (int idx = tid; idx < 16384; idx += nthreads) {
        const int chunk = idx >> 8;            // 0..63
        const int q = (idx >> 7) & 1;
        const int l = (idx >> 2) & 31;
        const int e = idx & 3;
        const int kc = chunk & 15, ng = chunk >> 4;
        const int re = q * 4 + e;
        const int nt = re >> 1, p = re & 1;
        const int k = kc * 8 + (l & 3) + 4 * p;
        const int n = ng * 32 + nt * 8 + (l >> 2);
        Bpu[idx] = f2tf32(w[k * H_DIM + n]);
    }
}

// ---------------- shared 16-kc double-buffered mma pass ----------------------
__device__ __forceinline__ void mma_tile_16kc(float cfr[2][4][4],
                                              const uint32_t* __restrict__ Au,
                                              const uint32_t* __restrict__ Bpu,
                                              int rm, int warp_n, int lane,
                                              int tg, int tq) {
    uint32_t abuf[2][2][4];
    uint32_t bbuf[2][8];

    auto load_frags = [&](int kc, int s) {
        const int k0 = kc * 8;
#pragma unroll
        for (int mt = 0; mt < 2; mt++) {
            const int rr = rm + mt * 16;
            abuf[s][mt][0] = Au[(rr + tg) * SA + k0 + tq];
            abuf[s][mt][1] = Au[(rr + tg + 8) * SA + k0 + tq];
            abuf[s][mt][2] = Au[(rr + tg) * SA + k0 + tq + 4];
            abuf[s][mt][3] = Au[(rr + tg + 8) * SA + k0 + tq + 4];
        }
        const uint32_t base = (uint32_t)((warp_n * 16 + kc) << 8);
        const uint4 q0 = *(const uint4*)(Bpu + base + (lane << 2));
        const uint4 q1 = *(const uint4*)(Bpu + base + 128 + (lane << 2));
        bbuf[s][0] = q0.x; bbuf[s][1] = q0.y; bbuf[s][2] = q0.z; bbuf[s][3] = q0.w;
        bbuf[s][4] = q1.x; bbuf[s][5] = q1.y; bbuf[s][6] = q1.z; bbuf[s][7] = q1.w;
    };

    load_frags(0, 0);
#pragma unroll
    for (int kc = 0; kc < 16; kc++) {
        const int cur = kc & 1, nxt = cur ^ 1;
        if (kc < 15) load_frags(kc + 1, nxt);
#pragma unroll
        for (int nt = 0; nt < 4; nt++) {
            mma_tf32(cfr[0][nt], abuf[cur][0], bbuf[cur][nt * 2], bbuf[cur][nt * 2 + 1]);
            mma_tf32(cfr[1][nt], abuf[cur][1], bbuf[cur][nt * 2], bbuf[cur][nt * 2 + 1]);
        }
    }
}

// ---------------- zero kernel ------------------------------------------------
__global__ void zero_all_kernel() {
    int i = blockIdx.x * blockDim.x + threadIdx.x;
    int stride = gridDim.x * blockDim.x;
    for (int k = i; k < N_LANE * H_DIM; k += stride) g_lane_agg[k] = 0.f;
    for (int k = i; k < N_AGENT * H_DIM; k += stride) g_agent_agg[k] = 0.f;
    for (int k = i; k < N_LANE; k += stride) g_deg_l[k] = 0.f;
    for (int k = i; k < N_AGENT; k += stride) g_deg_a[k] = 0.f;
}

// ---------------- fused tensor encoder (lane + agent), 512 threads -----------
// smem floats: A 16896 | Bperm 16384 | xs 2x960 | w1s 1024 | b1s 128 | b2s 128
#define ENC_TILE_NODES 6
#define ENC4_SMEM_FLOATS (16896 + 16384 + 1920 + 1024 + 128 + 128)
#define ENC4_SMEM_BYTES  (ENC4_SMEM_FLOATS * 4)

__global__ void __launch_bounds__(512, 1)
enc_both_kernel(const float* __restrict__ lane_x,
                const float* __restrict__ lw1, const float* __restrict__ lb1,
                const float* __restrict__ lw2, const float* __restrict__ lb2,
                const float* __restrict__ ax,
                const float* __restrict__ aw1, const float* __restrict__ ab1,
                const float* __restrict__ aw2, const float* __restrict__ ab2,
                float* __restrict__ ms_l, float* __restrict__ ms_a)
{
    extern __shared__ float smem[];
    float* A     = smem;               // tf32 bits during mma; f32 Dbuf after
    float* Bperm = A + 16896;
    float* xs    = Bperm + 16384;      // 2 x 960
    float* w1s   = xs + 1920;
    float* b1s   = w1s + 1024;
    float* b2s   = b1s + 128;

    uint32_t* Au  = (uint32_t*)A;
    uint32_t* Bpu = (uint32_t*)Bperm;

    const bool is_agent = blockIdx.x < AGENT_CTAS;
    const float* x_in = is_agent ? ax  : lane_x;
    const float* w1   = is_agent ? aw1 : lw1;
    const float* b1   = is_agent ? ab1 : lb1;
    const float* w2   = is_agent ? aw2 : lw2;
    const float* b2   = is_agent ? ab2 : lb2;
    float* ms_out     = is_agent ? ms_a : ms_l;
    const int n_nodes = is_agent ? N_AGENT : N_LANE;
    const int n_tiles = (n_nodes + ENC_TILE_NODES - 1) / ENC_TILE_NODES;
    const int cta0    = is_agent ? blockIdx.x : blockIdx.x - AGENT_CTAS;
    const int ncta    = is_agent ? AGENT_CTAS : TOTAL_CTAS - AGENT_CTAS;

    const int tid  = threadIdx.x;      // 0..511
    const int wid  = tid >> 5;         // 0..15
    const int lane = tid & 31;
    const int tg = lane >> 2;
    const int tq = lane & 3;
    const int warp_m = wid & 3;
    const int warp_n = wid >> 2;
    const int rm = warp_m * 32;

    load_Bperm(Bpu, w2, tid, 512);
    for (int i = tid; i < F_DIM * H_DIM; i += 512) w1s[i] = w1[i];
    if (tid < H_DIM) { b1s[tid] = b1[tid]; b2s[tid] = b2[tid]; }
    for (int i = tid; i < 8 * SA; i += 512)
        Au[120 * SA + i] = 0;          // zero pad rows 120..127 ONCE
    __syncthreads();                   // REQUIRED before reading w1s/b1s

    const int c    = tid & 127;
    const int rgrp = tid >> 7;         // 0..3, 30 rows each
    float wa[F_DIM];
#pragma unroll
    for (int f = 0; f < F_DIM; f++) wa[f] = w1s[f * H_DIM + c];
    const float b1v = b1s[c];

    auto prefetch = [&](int tile, int buf) {
        const int node0 = tile * ENC_TILE_NODES;
        for (int i = tid; i < 240; i += 512) {
            int j = i / 40;
            int nd = node0 + j; if (nd >= n_nodes) nd = n_nodes - 1;
            cp_async16(xs + buf * 960 + i * 4,
                       x_in + (size_t)nd * 160 + (i - j * 40) * 4);
        }
    };

    int buf = 0;
    if (cta0 < n_tiles) { prefetch(cta0, 0); }
    CP_COMMIT();

    for (int tile = cta0; tile < n_tiles; tile += ncta) {
        const int node0 = tile * ENC_TILE_NODES;

        CP_WAIT0();
        __syncthreads();
        const float* xc = xs + buf * 960;

        {
            int ntile = tile + ncta;
            if (ntile < n_tiles) prefetch(ntile, buf ^ 1);
            CP_COMMIT();
        }

        // ---- stage 1 ----
#pragma unroll 3
        for (int i = 0; i < 30; i++) {
            const int r = rgrp * 30 + i;
            const int j = r / 20;
            const float rx = xc[j * 160 + 152];
            const float ry = xc[j * 160 + 153];
            const float4* xp = (const float4*)(xc + r * 8);
            const float4 x0 = xp[0], x1 = xp[1];
            float s = b1v;
            s = fmaf(x0.x - rx, wa[0], s); s = fmaf(x0.y - ry, wa[1], s);
            s = fmaf(x0.z, wa[2], s); s = fmaf(x0.w, wa[3], s);
            s = fmaf(x1.x, wa[4], s); s = fmaf(x1.y, wa[5], s);
            s = fmaf(x1.z, wa[6], s); s = fmaf(x1.w, wa[7], s);
            Au[r * SA + c] = f2tf32(fmaxf(s, 0.f));
        }
        __syncthreads();

        // ---- mma ----
        float cfr[2][4][4];
#pragma unroll
        for (int mt = 0; mt < 2; mt++)
#pragma unroll
            for (int nt = 0; nt < 4; nt++)
#pragma unroll
                for (int q = 0; q < 4; q++) cfr[mt][nt][q] = 0.f;

        mma_tile_16kc(cfr, Au, Bpu, rm, warp_n, lane, tg, tq);
        __syncthreads();

        // ---- store C frags to Dbuf (skip pad rows >= 120) ----
#pragma unroll
        for (int mt = 0; mt < 2; mt++) {
            const int rr = rm + mt * 16 + tg;
#pragma unroll
            for (int nt = 0; nt < 4; nt++) {
                const int cc = warp_n * 32 + nt * 8 + 2 * tq;
                if (rr < 120)
                    *(float2*)(A + rr * SA + cc) =
                        make_float2(cfr[mt][nt][0], cfr[mt][nt][1]);
                if (rr + 8 < 120)
                    *(float2*)(A + (rr + 8) * SA + cc) =
                        make_float2(cfr[mt][nt][2], cfr[mt][nt][3]);
            }
        }
        __syncthreads();

        // ---- per-node max + bias + relu -> ms ----
        for (int task = tid; task < ENC_TILE_NODES * H_DIM; task += 512) {
            const int j = task >> 7, cc = task & 127;
            const int nd = node0 + j;
            if (nd < n_nodes) {
                float m = -3.4e38f;
                const float* dp = A + (j * 20) * SA + cc;
#pragma unroll
                for (int r = 0; r < 20; r++) m = fmaxf(m, dp[r * SA]);
                ms_out[(size_t)nd * H_DIM + cc] = fmaxf(m + b2s[cc], 0.f);
            }
        }
        __syncthreads();
        buf ^= 1;
    }
}

// ---------------- fused tensor MLP (lane + agent) ----------------------------
#define MLP2_SMEM_FLOATS (16896 + 16384 + 128)
#define MLP2_SMEM_BYTES  (MLP2_SMEM_FLOATS * 4)

__global__ void __launch_bounds__(512, 1)
mlp_both_kernel(const float* __restrict__ inL, const float* __restrict__ wL,
                const float* __restrict__ bL, float* __restrict__ outL,
                const float* __restrict__ inA, const float* __restrict__ wA,
                const float* __restrict__ bA, float* __restrict__ outA)
{
    extern __shared__ float smem[];
    float* A     = smem;
    float* Bperm = A + 16896;
    float* bs    = Bperm + 16384;
    uint32_t* Au  = (uint32_t*)A;
    uint32_t* Bpu = (uint32_t*)Bperm;

    const bool is_agent = blockIdx.x >= LANE_BLKS;
    const float* in_feat = is_agent ? inA : inL;
    const float* w       = is_agent ? wA : wL;
    const float* b       = is_agent ? bA : bL;
    float* out           = is_agent ? outA : outL;
    const int n_nodes    = is_agent ? N_AGENT : N_LANE;
    const int n0 = (is_agent ? (blockIdx.x - LANE_BLKS) : blockIdx.x) * 128;

    const int tid  = threadIdx.x;
    const int wid  = tid >> 5;
    const int lane = tid & 31;
    const int tg = lane >> 2;
    const int tq = lane & 3;
    const int warp_m = wid & 3;
    const int warp_n = wid >> 2;
    const int rm = warp_m * 32;

    load_Bperm(Bpu, w, tid, 512);
    if (tid < H_DIM) bs[tid] = b[tid];

    {
        const int c  = tid & 127;
        const int r0 = (tid >> 7) * 32;
        for (int i = 0; i < 32; i++) {
            int r = r0 + i;
            int idx = n0 + r; if (idx >= n_nodes) idx = n_nodes - 1;
            Au[r * SA + c] = f2tf32(in_feat[(size_t)idx * H_DIM + c]);
        }
    }
    __syncthreads();

    float cfr[2][4][4];
#pragma unroll
    for (int mt = 0; mt < 2; mt++)
#pragma unroll
        for (int nt = 0; nt < 4; nt++)
#pragma unroll
            for (int q = 0; q < 4; q++) cfr[mt][nt][q] = 0.f;

    mma_tile_16kc(cfr, Au, Bpu, rm, warp_n, lane, tg, tq);

#pragma unroll
    for (int mt = 0; mt < 2; mt++) {
        const int rr = rm + mt * 16 + tg;
#pragma unroll
        for (int nt = 0; nt < 4; nt++) {
            const int cc = warp_n * 32 + nt * 8 + 2 * tq;
            const float2 bv = make_float2(bs[cc], bs[cc + 1]);
            const int nd0 = n0 + rr;
            if (nd0 < n_nodes)
                *(float2*)(out + (size_t)nd0 * H_DIM + cc) =
                    make_float2(fmaxf(cfr[mt][nt][0] + bv.x, 0.f),
                                fmaxf(cfr[mt][nt][1] + bv.y, 0.f));
            const int nd1 = nd0 + 8;
            if (nd1 < n_nodes)
                *(float2*)(out + (size_t)nd1 * H_DIM + cc) =
                    make_float2(fmaxf(cfr[mt][nt][2] + bv.x, 0.f),
                                fmaxf(cfr[mt][nt][3] + bv.y, 0.f));
        }
    }
}

// ---------------- fused tensor GNN (lane LL + agent AA, AA zeroes agg after) -
#define GNN2_SMEM_FLOATS (16896 + 16384 + 128 + 128)
#define GNN2_SMEM_BYTES  (GNN2_SMEM_FLOATS * 4)

__device__ __forceinline__ void gnn_body(
    const float* __restrict__ node_in, float* __restrict__ agg,
    float* __restrict__ deg,
    const float* __restrict__ w1, const float* __restrict__ b1,
    const float* __restrict__ w2, const float* __restrict__ b2,
    float* __restrict__ out, int n_nodes, int n0, bool zero_after)
{
    extern __shared__ float smem[];
    float* A     = smem;
    float* Bperm = A + 16896;
    float* bs1   = Bperm + 16384;
    float* bs2   = bs1 + 128;
    uint32_t* Au  = (uint32_t*)A;
    uint32_t* Bpu = (uint32_t*)Bperm;

    const int tid  = threadIdx.x;
    const int wid  = tid >> 5;
    const int lane = tid & 31;
    const int tg = lane >> 2;
    const int tq = lane & 3;
    const int warp_m = wid & 3;
    const int warp_n = wid >> 2;
    const int rm = warp_m * 32;

    const int c  = tid & 127;
    const int r0 = (tid >> 7) * 32;

    // phase 0: Bp = w1[0:128], A = node rows
    load_Bperm(Bpu, w1, tid, 512);
    if (tid < H_DIM) { bs1[tid] = b1[tid]; bs2[tid] = b2[tid]; }
    for (int i = 0; i < 32; i++) {
        int r = r0 + i;
        int idx = n0 + r; if (idx >= n_nodes) idx = n_nodes - 1;
        Au[r * SA + c] = f2tf32(node_in[(size_t)idx * H_DIM + c]);
    }
    __syncthreads();

    float cfr[2][4][4];
#pragma unroll
    for (int mt = 0; mt < 2; mt++)
#pragma unroll
        for (int nt = 0; nt < 4; nt++)
#pragma unroll
            for (int q = 0; q < 4; q++) cfr[mt][nt][q] = 0.f;

    mma_tile_16kc(cfr, Au, Bpu, rm, warp_n, lane, tg, tq);
    __syncthreads();

    // phase 2: Bp = w1[128:256], A = agg/deg.
    // agg zero-after-read is per-thread-private (same thread reads & zeroes its
    // own (idx,c) element) -> safe. deg is read by 128 threads per row, so its
    // zeroing is DEFERRED until after the __syncthreads() below (round-10 bug:
    // zeroing it here raced with other warps' reads).
    load_Bperm(Bpu, w1 + 128 * H_DIM, tid, 512);
    for (int i = 0; i < 32; i++) {
        int r = r0 + i;
        int idx = n0 + r;
        bool valid = idx < n_nodes;
        if (!valid) idx = n_nodes - 1;
        const float dv = deg[idx];
        const float invd = 1.0f / fmaxf(dv, 1.0f);
        const float av = agg[(size_t)idx * H_DIM + c];
        Au[r * SA + c] = f2tf32(av * invd);
        if (zero_after && valid)
            agg[(size_t)idx * H_DIM + c] = 0.f;
    }
    __syncthreads();
    if (zero_after && c == 0) {
        for (int i = 0; i < 32; i++) {
            int idx = n0 + r0 + i;
            if (idx < n_nodes) deg[idx] = 0.f;
        }
    }

    mma_tile_16kc(cfr, Au, Bpu, rm, warp_n, lane, tg, tq);
    __syncthreads();

    // phase 4: h = relu(cfr + b1) -> A (tf32); Bp = w2
#pragma unroll
    for (int mt = 0; mt < 2; mt++) {
        const int rr = rm + mt * 16 + tg;
#pragma unroll
        for (int nt = 0; nt < 4; nt++) {
            const int cc = warp_n * 32 + nt * 8 + 2 * tq;
            Au[rr * SA + cc]     = f2tf32(fmaxf(cfr[mt][nt][0] + bs1[cc], 0.f));
            Au[rr * SA + cc + 1] = f2tf32(fmaxf(cfr[mt][nt][1] + bs1[cc + 1], 0.f));
            Au[(rr + 8) * SA + cc]     = f2tf32(fmaxf(cfr[mt][nt][2] + bs1[cc], 0.f));
            Au[(rr + 8) * SA + cc + 1] = f2tf32(fmaxf(cfr[mt][nt][3] + bs1[cc + 1], 0.f));
        }
    }
    load_Bperm(Bpu, w2, tid, 512);
    __syncthreads();

    // phase 6: layer 2 mma
#pragma unroll
    for (int mt = 0; mt < 2; mt++)
#pragma unroll
        for (int nt = 0; nt < 4; nt++)
#pragma unroll
            for (int q = 0; q < 4; q++) cfr[mt][nt][q] = 0.f;

    mma_tile_16kc(cfr, Au, Bpu, rm, warp_n, lane, tg, tq);

    // epilogue: out = node + relu(cfr + b2)
#pragma unroll
    for (int mt = 0; mt < 2; mt++) {
        const int rr = rm + mt * 16 + tg;
#pragma unroll
        for (int nt = 0; nt < 4; nt++) {
            const int cc = warp_n * 32 + nt * 8 + 2 * tq;
            const float2 bv = make_float2(bs2[cc], bs2[cc + 1]);
            const int nd0 = n0 + rr;
            if (nd0 < n_nodes) {
                const float2 nv = *(const float2*)(node_in + (size_t)nd0 * H_DIM + cc);
                *(float2*)(out + (size_t)nd0 * H_DIM + cc) =
                    make_float2(nv.x + fmaxf(cfr[mt][nt][0] + bv.x, 0.f),
                                nv.y + fmaxf(cfr[mt][nt][1] + bv.y, 0.f));
            }
            const int nd1 = nd0 + 8;
            if (nd1 < n_nodes) {
                const float2 nv = *(const float2*)(node_in + (size_t)nd1 * H_DIM + cc);
                *(float2*)(out + (size_t)nd1 * H_DIM + cc) =
                    make_float2(nv.x + fmaxf(cfr[mt][nt][2] + bv.x, 0.f),
                                nv.y + fmaxf(cfr[mt][nt][3] + bv.y, 0.f));
            }
        }
    }
}

__global__ void __launch_bounds__(512, 1)
gnn_both_kernel(const float* __restrict__ lane_in, float* __restrict__ lane_agg,
                float* __restrict__ deg_l,
                const float* __restrict__ ll_w1, const float* __restrict__ ll_b1,
                const float* __restrict__ ll_w2, const float* __restrict__ ll_b2,
                float* __restrict__ lane_out,
                const float* __restrict__ agent_in, float* __restrict__ agent_agg,
                float* __restrict__ deg_a,
                const float* __restrict__ aa_w1, const float* __restrict__ aa_b1,
                const float* __restrict__ aa_w2, const float* __restrict__ aa_b2,
                float* __restrict__ agent_out)
{
    if (blockIdx.x < LANE_BLKS) {
        gnn_body(lane_in, lane_agg, deg_l, ll_w1, ll_b1, ll_w2, ll_b2,
                 lane_out, N_LANE, blockIdx.x * 128, false);
    } else {
        gnn_body(agent_in, agent_agg, deg_a, aa_w1, aa_b1, aa_w2, aa_b2,
                 agent_out, N_AGENT, (blockIdx.x - LANE_BLKS) * 128, true);
    }
}

__global__ void __launch_bounds__(512, 1)
gnn_la_kernel(const float* __restrict__ node_in, float* __restrict__ agg,
              float* __restrict__ deg,
              const float* __restrict__ w1, const float* __restrict__ b1,
              const float* __restrict__ w2, const float* __restrict__ b2,
              float* __restrict__ out)
{
    gnn_body(node_in, agg, deg, w1, b1, w2, b2, out, N_AGENT,
             blockIdx.x * 128, false);
}

// ---------------- fused edge scatter (LL + AA) -------------------------------
__global__ void scatter_both_kernel(const int* __restrict__ e_ll,
                                    const int* __restrict__ e_aa,
                                    const float* __restrict__ lane_feat,
                                    float* __restrict__ lane_agg,
                                    float* __restrict__ deg_l,
                                    const float* __restrict__ agent_feat,
                                    float* __restrict__ agent_agg,
                                    float* __restrict__ deg_a)
{
    const int warp = (blockIdx.x * blockDim.x + threadIdx.x) >> 5;
    const int lane = threadIdx.x & 31;
    int s, d;
    const float* feat;
    float* agg;
    float* deg;
    if (warp < E_LL) {
        s = e_ll[warp]; d = e_ll[E_LL + warp];
        feat = lane_feat; agg = lane_agg; deg = deg_l;
    } else if (warp < E_LL + E_AA) {
        const int w2 = warp - E_LL;
        s = e_aa[w2]; d = e_aa[E_AA + w2];
        feat = agent_feat; agg = agent_agg; deg = deg_a;
    } else return;
    const float4 v = ((const float4*)(feat + (size_t)s * H_DIM))[lane];
    float4* a = ((float4*)(agg + (size_t)d * H_DIM)) + lane;
    asm volatile("red.global.add.v4.f32 [%0], {%1,%2,%3,%4};"
                 :: "l"(a), "f"(v.x), "f"(v.y), "f"(v.z), "f"(v.w) : "memory");
    if (lane == 0) atomicAdd(deg + d, 1.0f);
}

__global__ void scatter_la_kernel(const int* __restrict__ e_la,
                                  const float* __restrict__ feat,
                                  float* __restrict__ agg,
                                  float* __restrict__ deg)
{
    const int warp = (blockIdx.x * blockDim.x + threadIdx.x) >> 5;
    const int lane = threadIdx.x & 31;
    if (warp >= E_LA) return;
    const int s = e_la[warp];
    const int d = e_la[E_LA + warp];
    const float4 v = ((const float4*)(feat + (size_t)s * H_DIM))[lane];
    float4* a = ((float4*)(agg + (size_t)d * H_DIM)) + lane;
    asm volatile("red.global.add.v4.f32 [%0], {%1,%2,%3,%4};"
                 :: "l"(a), "f"(v.x), "f"(v.y), "f"(v.z), "f"(v.w) : "memory");
    if (lane == 0) atomicAdd(deg + d, 1.0f);
}

// ---------------- launch -----------------------------------------------------
extern "C" void kernel_launch(void* const* d_in, const int* in_sizes, int n_in,
                              void* d_out, int out_size)
{
    const float* lane_points   = (const float*)d_in[0];
    const float* agent_history = (const float*)d_in[1];
    const int* e_ll = (const int*)d_in[2];
    const int* e_aa = (const int*)d_in[3];
    const int* e_la = (const int*)d_in[4];
    const float* lw1 = (const float*)d_in[5];
    const float* lb1 = (const float*)d_in[6];
    const float* lw2 = (const float*)d_in[7];
    const float* lb2 = (const float*)d_in[8];
    const float* lw3 = (const float*)d_in[9];
    const float* lb3 = (const float*)d_in[10];
    const float* aw1 = (const float*)d_in[11];
    const float* ab1 = (const float*)d_in[12];
    const float* aw2 = (const float*)d_in[13];
    const float* ab2 = (const float*)d_in[14];
    const float* aw3 = (const float*)d_in[15];
    const float* ab3 = (const float*)d_in[16];
    const float* ll_w1 = (const float*)d_in[17];
    const float* ll_b1 = (const float*)d_in[18];
    const float* ll_w2 = (const float*)d_in[19];
    const float* ll_b2 = (const float*)d_in[20];
    const float* aa_w1 = (const float*)d_in[21];
    const float* aa_b1 = (const float*)d_in[22];
    const float* aa_w2 = (const float*)d_in[23];
    const float* aa_b2 = (const float*)d_in[24];
    const float* la_w1 = (const float*)d_in[25];
    const float* la_b1 = (const float*)d_in[26];
    const float* la_w2 = (const float*)d_in[27];
    const float* la_b2 = (const float*)d_in[28];

    float* out = (float*)d_out;
    float* lane_out  = out;
    float* agent_out = out + (size_t)N_LANE * H_DIM;

    float *p_lane_enc, *p_agent_enc, *p_lane_agg, *p_agent_agg;
    float *p_ms_l, *p_ms_a, *p_deg_l, *p_deg_a;
    cudaGetSymbolAddress((void**)&p_lane_enc,  g_lane_enc);
    cudaGetSymbolAddress((void**)&p_agent_enc, g_agent_enc);
    cudaGetSymbolAddress((void**)&p_lane_agg,  g_lane_agg);
    cudaGetSymbolAddress((void**)&p_agent_agg, g_agent_agg);
    cudaGetSymbolAddress((void**)&p_ms_l,      g_ms_l);
    cudaGetSymbolAddress((void**)&p_ms_a,      g_ms_a);
    cudaGetSymbolAddress((void**)&p_deg_l,     g_deg_l);
    cudaGetSymbolAddress((void**)&p_deg_a,     g_deg_a);

    cudaFuncSetAttribute(enc_both_kernel, cudaFuncAttributeMaxDynamicSharedMemorySize, ENC4_SMEM_BYTES);
    cudaFuncSetAttribute(mlp_both_kernel, cudaFuncAttributeMaxDynamicSharedMemorySize, MLP2_SMEM_BYTES);
    cudaFuncSetAttribute(gnn_both_kernel, cudaFuncAttributeMaxDynamicSharedMemorySize, GNN2_SMEM_BYTES);
    cudaFuncSetAttribute(gnn_la_kernel,   cudaFuncAttributeMaxDynamicSharedMemorySize, GNN2_SMEM_BYTES);

    // 1. zero aggregation buffers
    zero_all_kernel<<<2048, 256>>>();

    // 2. fused encoders (agent CTAs 0..24, lane CTAs 25..147)
    enc_both_kernel<<<TOTAL_CTAS, 512, ENC4_SMEM_BYTES>>>(
        lane_points, lw1, lb1, lw2, lb2,
        agent_history, aw1, ab1, aw2, ab2, p_ms_l, p_ms_a);

    // 3. fused stage-3 MLPs
    mlp_both_kernel<<<LANE_BLKS + AGENT_BLKS, 512, MLP2_SMEM_BYTES>>>(
        p_ms_l, lw3, lb3, p_lane_enc,
        p_ms_a, aw3, ab3, p_agent_enc);

    // 4. fused LL + AA scatter
    scatter_both_kernel<<<(E_LL + E_AA + 7) / 8, 256>>>(
        e_ll, e_aa, p_lane_enc, p_lane_agg, p_deg_l,
        p_agent_enc, p_agent_agg, p_deg_a);

    // 5. fused LL + AA GNN (AA half zeroes agent agg/deg after reading)
    gnn_both_kernel<<<LANE_BLKS + AGENT_BLKS, 512, GNN2_SMEM_BYTES>>>(
        p_lane_enc, p_lane_agg, p_deg_l, ll_w1, ll_b1, ll_w2, ll_b2, lane_out,
        p_agent_enc, p_agent_agg, p_deg_a, aa_w1, aa_b1, aa_w2, aa_b2, agent_out);

    // 6. LA scatter (source = updated lane)
    scatter_la_kernel<<<(E_LA + 7) / 8, 256>>>(e_la, lane_out, p_agent_agg, p_deg_a);

    // 7. LA GNN (in-place on agent_out)
    gnn_la_kernel<<<AGENT_BLKS, 512, GNN2_SMEM_BYTES>>>(
        agent_out, p_agent_agg, p_deg_a, la_w1, la_b1, la_w2, la_b2, agent_out);
}